// round 3
// baseline (speedup 1.0000x reference)
#include <cuda_runtime.h>
#include <math.h>

// Problem dims (CrossModalRouter): T=64 tasks, B=4096, TD=512, HD=256, VD=484
#define T_TASKS 64
#define B_ROWS  4096
#define TD      512
#define HD      256
#define VD      484

// Tiling
#define BM 64          // batch rows per block
#define KC 32          // K chunk
#define NBLK (B_ROWS / BM)   // 64 batch tiles

// Shared memory layout (in floats)
#define BS_STRIDE 257  // padded stride for B tile: bank = (k + n) % 32 -> conflict-free
#define HS_OFF   0
#define BS_OFF   (BM * HD)                   // 16384
#define AS_OFF   (BS_OFF + KC * BS_STRIDE)   // 16384 + 8224
#define RED_OFF  (AS_OFF + BM * KC)          // + 2048
#define SMEM_FLOATS (RED_OFF + 8)
#define SMEM_BYTES  (SMEM_FLOATS * 4)        // 106,656 B -> 2 blocks/SM

// Global scratch (no cudaMalloc allowed): per-block partial sums + centroid norms
__device__ float g_partial[T_TASKS * NBLK];
__device__ float g_cnorm[T_TASKS];

// ---------------------------------------------------------------------------
// Kernel 0: clamped centroid norms per task
// ---------------------------------------------------------------------------
__global__ void init_cnorm_kernel(const float* __restrict__ cent) {
    int t = blockIdx.x;
    float s = 0.f;
    for (int n = threadIdx.x; n < VD; n += 128) {
        float c = cent[t * VD + n];
        s = fmaf(c, c, s);
    }
#pragma unroll
    for (int off = 16; off > 0; off >>= 1)
        s += __shfl_xor_sync(0xffffffffu, s, off);
    __shared__ float ws[4];
    int lane = threadIdx.x & 31, w = threadIdx.x >> 5;
    if (lane == 0) ws[w] = s;
    __syncthreads();
    if (threadIdx.x == 0) {
        float tot = ws[0] + ws[1] + ws[2] + ws[3];
        g_cnorm[t] = fmaxf(sqrtf(tot), 1e-8f);
    }
}

// ---------------------------------------------------------------------------
// Kernel 1: fused  Linear1 -> LayerNorm -> GELU(erf) -> Linear2 -> cosine fold
// grid = (NBLK, T), block = 256.  Each thread owns an 8x8 register tile.
// Warp rg owns rows rg*8 .. rg*8+7 completely (lane cg holds cols cg+32j),
// so LayerNorm and the cosine reductions are pure warp shuffles.
// ---------------------------------------------------------------------------
__global__ __launch_bounds__(256, 2)
void router_kernel(const float* __restrict__ t_feat,
                   const float* __restrict__ W1,
                   const float* __restrict__ b1,
                   const float* __restrict__ gamma,
                   const float* __restrict__ beta,
                   const float* __restrict__ W2,
                   const float* __restrict__ b2,
                   const float* __restrict__ cent) {
    extern __shared__ float smem[];
    float* Hs  = smem + HS_OFF;   // [BM][HD] post-GELU activations
    float* Bs  = smem + BS_OFF;   // [KC][BS_STRIDE] weight tile (transposed)
    float* As  = smem + AS_OFF;   // [BM][KC] activation tile
    float* red = smem + RED_OFF;  // [8] per-warp partials

    const int tid = threadIdx.x;
    const int rg  = tid >> 5;     // warp id -> row group
    const int cg  = tid & 31;     // lane -> base column
    const int t   = blockIdx.y;
    const int brow0 = blockIdx.x * BM;

    const float* Arow = t_feat + (size_t)brow0 * TD;
    const float* W1t  = W1 + (size_t)t * HD * TD;

    // ===================== GEMM1: h = t_feat @ W1^T ========================
    float acc[8][8];
#pragma unroll
    for (int i = 0; i < 8; i++)
#pragma unroll
        for (int j = 0; j < 8; j++) acc[i][j] = 0.f;

    for (int k0 = 0; k0 < TD; k0 += KC) {
        // stage A tile [64 rows x 32 k] (float4, coalesced)
#pragma unroll
        for (int q = tid; q < BM * (KC / 4); q += 256) {
            int row = q >> 3, kq = q & 7;
            float4 v = *reinterpret_cast<const float4*>(Arow + (size_t)row * TD + k0 + kq * 4);
            *reinterpret_cast<float4*>(As + row * KC + kq * 4) = v;
        }
        // stage W1 tile transposed: Bs[k][n], n = hidden col (coalesced 128B/n)
#pragma unroll
        for (int q = tid; q < HD * (KC / 4); q += 256) {
            int n = q >> 3, kq = q & 7;
            float4 v = *reinterpret_cast<const float4*>(W1t + (size_t)n * TD + k0 + kq * 4);
            int k = kq * 4;
            Bs[(k + 0) * BS_STRIDE + n] = v.x;
            Bs[(k + 1) * BS_STRIDE + n] = v.y;
            Bs[(k + 2) * BS_STRIDE + n] = v.z;
            Bs[(k + 3) * BS_STRIDE + n] = v.w;
        }
        __syncthreads();
#pragma unroll 8
        for (int k = 0; k < KC; k++) {
            float a[8], b[8];
#pragma unroll
            for (int i = 0; i < 8; i++) a[i] = As[(rg * 8 + i) * KC + k];   // broadcast
#pragma unroll
            for (int j = 0; j < 8; j++) b[j] = Bs[k * BS_STRIDE + cg + 32 * j];
#pragma unroll
            for (int i = 0; i < 8; i++)
#pragma unroll
                for (int j = 0; j < 8; j++)
                    acc[i][j] = fmaf(a[i], b[j], acc[i][j]);
        }
        __syncthreads();
    }

    // ============ bias + LayerNorm (warp-local) + exact GELU ==============
    {
        float b1c[8], gm[8], bt[8];
#pragma unroll
        for (int j = 0; j < 8; j++) {
            int c = cg + 32 * j;
            b1c[j] = b1[t * HD + c];
            gm[j]  = gamma[t * HD + c];
            bt[j]  = beta[t * HD + c];
        }
#pragma unroll
        for (int i = 0; i < 8; i++) {
            float s = 0.f, s2 = 0.f;
#pragma unroll
            for (int j = 0; j < 8; j++) {
                float x = acc[i][j] + b1c[j];
                acc[i][j] = x;
                s += x;
                s2 = fmaf(x, x, s2);
            }
#pragma unroll
            for (int off = 16; off > 0; off >>= 1) {
                s  += __shfl_xor_sync(0xffffffffu, s, off);
                s2 += __shfl_xor_sync(0xffffffffu, s2, off);
            }
            float mu   = s * (1.f / HD);
            float var  = s2 * (1.f / HD) - mu * mu;
            float rstd = rsqrtf(var + 1e-5f);
            int r = rg * 8 + i;
#pragma unroll
            for (int j = 0; j < 8; j++) {
                float x = (acc[i][j] - mu) * rstd * gm[j] + bt[j];
                float g = 0.5f * x * (1.f + erff(x * 0.70710678118654752f));
                Hs[r * HD + cg + 32 * j] = g;
            }
        }
    }
    __syncthreads();

    // ========= GEMM2 (VD in two 256-col tiles) + cosine fold ==============
    float num[8], sq[8];
#pragma unroll
    for (int i = 0; i < 8; i++) { num[i] = 0.f; sq[i] = 0.f; }

    const float* W2t = W2 + (size_t)t * VD * HD;

#pragma unroll 1
    for (int nt = 0; nt < 2; nt++) {
        const int nbase = nt * 256;
        float acc2[8][8];
#pragma unroll
        for (int i = 0; i < 8; i++)
#pragma unroll
            for (int j = 0; j < 8; j++) acc2[i][j] = 0.f;

        for (int k0 = 0; k0 < HD; k0 += KC) {
            // stage W2 tile transposed: Bs[k][nl], OOB cols -> 0
#pragma unroll
            for (int q = tid; q < 256 * (KC / 4); q += 256) {
                int nl = q >> 3, kq = q & 7;
                int n = nbase + nl;
                float4 v = make_float4(0.f, 0.f, 0.f, 0.f);
                if (n < VD)
                    v = *reinterpret_cast<const float4*>(W2t + (size_t)n * HD + k0 + kq * 4);
                int k = kq * 4;
                Bs[(k + 0) * BS_STRIDE + nl] = v.x;
                Bs[(k + 1) * BS_STRIDE + nl] = v.y;
                Bs[(k + 2) * BS_STRIDE + nl] = v.z;
                Bs[(k + 3) * BS_STRIDE + nl] = v.w;
            }
            __syncthreads();
#pragma unroll 8
            for (int k = 0; k < KC; k++) {
                float a[8], b[8];
#pragma unroll
                for (int i = 0; i < 8; i++) a[i] = Hs[(rg * 8 + i) * HD + k0 + k]; // broadcast
#pragma unroll
                for (int j = 0; j < 8; j++) b[j] = Bs[k * BS_STRIDE + cg + 32 * j];
#pragma unroll
                for (int i = 0; i < 8; i++)
#pragma unroll
                    for (int j = 0; j < 8; j++)
                        acc2[i][j] = fmaf(a[i], b[j], acc2[i][j]);
            }
            __syncthreads();
        }
        // fold v = acc2 + b2 into cosine numerator and ||v||^2 (v never stored)
#pragma unroll
        for (int j = 0; j < 8; j++) {
            int n = nbase + cg + 32 * j;
            if (n < VD) {
                float bb = b2[t * VD + n];
                float cc = cent[t * VD + n];
#pragma unroll
                for (int i = 0; i < 8; i++) {
                    float v = acc2[i][j] + bb;
                    num[i] = fmaf(v, cc, num[i]);
                    sq[i]  = fmaf(v, v, sq[i]);
                }
            }
        }
    }

    // ================= per-row cosine, block partial =======================
    float cn = g_cnorm[t];
    float rowsum = 0.f;
#pragma unroll
    for (int i = 0; i < 8; i++) {
        float nu = num[i], s = sq[i];
#pragma unroll
        for (int off = 16; off > 0; off >>= 1) {
            nu += __shfl_xor_sync(0xffffffffu, nu, off);
            s  += __shfl_xor_sync(0xffffffffu, s, off);
        }
        float vn = fmaxf(sqrtf(s), 1e-8f);
        rowsum += 1.f - nu / (vn * cn);
    }
    if (cg == 0) red[rg] = rowsum;
    __syncthreads();
    if (tid == 0) {
        float bs = 0.f;
#pragma unroll
        for (int w = 0; w < 8; w++) bs += red[w];
        g_partial[t * NBLK + blockIdx.x] = bs;   // deterministic slot write, no atomics
    }
}

// ---------------------------------------------------------------------------
// Kernel 2: finalize -> distances[T] (mean over B) + argmin
// ---------------------------------------------------------------------------
__global__ void finalize_kernel(float* __restrict__ out, int out_size) {
    __shared__ float dist[T_TASKS];
    int t = threadIdx.x;
    if (t < T_TASKS) {
        float s = 0.f;
#pragma unroll
        for (int b = 0; b < NBLK; b++) s += g_partial[t * NBLK + b];
        float d = s * (1.0f / (float)B_ROWS);
        dist[t] = d;
        if (out_size >= T_TASKS) out[t] = d;
    }
    __syncthreads();
    if (t == 0) {
        int best = 0;
        float bv = dist[0];
        for (int i = 1; i < T_TASKS; i++)
            if (dist[i] < bv) { bv = dist[i]; best = i; }   // first-min tie-break (jnp.argmin)
        if (out_size >= T_TASKS + 1)      out[T_TASKS] = (float)best;
        else if (out_size >= 1 && out_size < T_TASKS) out[0] = (float)best;
    }
}

// ---------------------------------------------------------------------------
extern "C" void kernel_launch(void* const* d_in, const int* in_sizes, int n_in,
                              void* d_out, int out_size) {
    const float* t_feat = (const float*)d_in[0];
    const float* W1     = (const float*)d_in[1];
    const float* b1     = (const float*)d_in[2];
    const float* gamma  = (const float*)d_in[3];
    const float* beta   = (const float*)d_in[4];
    const float* W2     = (const float*)d_in[5];
    const float* b2     = (const float*)d_in[6];
    const float* cent   = (const float*)d_in[7];

    cudaFuncSetAttribute(router_kernel,
                         cudaFuncAttributeMaxDynamicSharedMemorySize, SMEM_BYTES);

    init_cnorm_kernel<<<T_TASKS, 128>>>(cent);
    dim3 grid(NBLK, T_TASKS);
    router_kernel<<<grid, 256, SMEM_BYTES>>>(t_feat, W1, b1, gamma, beta, W2, b2, cent);
    finalize_kernel<<<1, 64>>>((float*)d_out, out_size);
}

// round 5
// speedup vs baseline: 1.8156x; 1.8156x over previous
#include <cuda_runtime.h>
#include <math.h>

// Problem dims (CrossModalRouter): T=64 tasks, B=4096, TD=512, HD=256, VD=484
#define T_TASKS 64
#define B_ROWS  4096
#define TD      512
#define HD      256
#define VD      484

// Tiling
#define BM 64          // batch rows per block
#define KC 32          // K chunk
#define NBLK (B_ROWS / BM)   // 64 batch tiles

// Shared memory layout (in floats)
// BS_STRIDE must be EVEN so LDS.64 pair-loads (offset k*S + 2*cg + 64*j) stay
// 8-byte aligned for every k. 258: read phases conflict-free (contiguous 256B
// per 16-lane phase); staging stores see a benign 2-way conflict.
#define BS_STRIDE 258
#define HS_OFF   0
#define BS_OFF   (BM * HD)                   // 16384
#define AS_OFF   (BS_OFF + KC * BS_STRIDE)   // + 8256
#define RED_OFF  (AS_OFF + BM * KC)          // + 2048
#define SMEM_FLOATS (RED_OFF + 8)
#define SMEM_BYTES  (SMEM_FLOATS * 4)        // 106,784 B -> 2 blocks/SM

typedef unsigned long long ull;

// packed dual FMA: d.lo += a.lo*b.lo ; d.hi += a.hi*b.hi   (SASS FFMA2)
__device__ __forceinline__ void fma2(ull& d, ull a, ull b) {
    asm("fma.rn.f32x2 %0, %1, %2, %0;" : "+l"(d) : "l"(a), "l"(b));
}
__device__ __forceinline__ ull splat2(float v) {
    ull r;
    asm("mov.b64 %0, {%1, %1};" : "=l"(r) : "r"(__float_as_uint(v)));
    return r;
}
__device__ __forceinline__ float2 unpack2(ull v) {
    float2 f;
    asm("mov.b64 {%0, %1}, %2;" : "=f"(f.x), "=f"(f.y) : "l"(v));
    return f;
}

// Global scratch (no cudaMalloc allowed): per-block partial sums + centroid norms
__device__ float g_partial[T_TASKS * NBLK];
__device__ float g_cnorm[T_TASKS];

// ---------------------------------------------------------------------------
// Kernel 0: clamped centroid norms per task
// ---------------------------------------------------------------------------
__global__ void init_cnorm_kernel(const float* __restrict__ cent) {
    int t = blockIdx.x;
    float s = 0.f;
    for (int n = threadIdx.x; n < VD; n += 128) {
        float c = cent[t * VD + n];
        s = fmaf(c, c, s);
    }
#pragma unroll
    for (int off = 16; off > 0; off >>= 1)
        s += __shfl_xor_sync(0xffffffffu, s, off);
    __shared__ float ws[4];
    int lane = threadIdx.x & 31, w = threadIdx.x >> 5;
    if (lane == 0) ws[w] = s;
    __syncthreads();
    if (threadIdx.x == 0) {
        float tot = ws[0] + ws[1] + ws[2] + ws[3];
        g_cnorm[t] = fmaxf(sqrtf(tot), 1e-8f);
    }
}

// ---------------------------------------------------------------------------
// Kernel 1: fused  Linear1 -> LayerNorm -> GELU(erf) -> Linear2 -> cosine fold
// grid = (NBLK, T), block = 256.  Each thread owns 8 rows x 4 column-PAIRS
// (cols {2cg+64j, 2cg+1+64j}) computed with packed fma.rn.f32x2.
// Warp rg owns rows rg*8..rg*8+7 completely -> LayerNorm/cosine = shuffles.
// ---------------------------------------------------------------------------
__global__ __launch_bounds__(256, 2)
void router_kernel(const float* __restrict__ t_feat,
                   const float* __restrict__ W1,
                   const float* __restrict__ b1,
                   const float* __restrict__ gamma,
                   const float* __restrict__ beta,
                   const float* __restrict__ W2,
                   const float* __restrict__ b2,
                   const float* __restrict__ cent) {
    extern __shared__ float smem[];
    float* Hs  = smem + HS_OFF;   // [BM][HD] post-GELU activations
    float* Bs  = smem + BS_OFF;   // [KC][BS_STRIDE] weight tile (transposed)
    float* As  = smem + AS_OFF;   // [BM][KC] activation tile
    float* red = smem + RED_OFF;  // [8] per-warp partials

    const int tid = threadIdx.x;
    const int rg  = tid >> 5;     // warp id -> row group
    const int cg  = tid & 31;     // lane -> column-pair base (2*cg)
    const int t   = blockIdx.y;
    const int brow0 = blockIdx.x * BM;

    const float* Arow = t_feat + (size_t)brow0 * TD;
    const float* W1t  = W1 + (size_t)t * HD * TD;

    // ===================== GEMM1: h = t_feat @ W1^T ========================
    ull acc[8][4];
#pragma unroll
    for (int i = 0; i < 8; i++)
#pragma unroll
        for (int j = 0; j < 4; j++) acc[i][j] = 0ull;

    for (int k0 = 0; k0 < TD; k0 += KC) {
        // stage A tile [64 rows x 32 k] (float4, coalesced)
#pragma unroll
        for (int q = tid; q < BM * (KC / 4); q += 256) {
            int row = q >> 3, kq = q & 7;
            float4 v = *reinterpret_cast<const float4*>(Arow + (size_t)row * TD + k0 + kq * 4);
            *reinterpret_cast<float4*>(As + row * KC + kq * 4) = v;
        }
        // stage W1 tile transposed: Bs[k][n], n = hidden col
#pragma unroll
        for (int q = tid; q < HD * (KC / 4); q += 256) {
            int n = q >> 3, kq = q & 7;
            float4 v = *reinterpret_cast<const float4*>(W1t + (size_t)n * TD + k0 + kq * 4);
            int k = kq * 4;
            Bs[(k + 0) * BS_STRIDE + n] = v.x;
            Bs[(k + 1) * BS_STRIDE + n] = v.y;
            Bs[(k + 2) * BS_STRIDE + n] = v.z;
            Bs[(k + 3) * BS_STRIDE + n] = v.w;
        }
        __syncthreads();
#pragma unroll 8
        for (int k = 0; k < KC; k++) {
            ull bv[4], av[8];
#pragma unroll
            for (int j = 0; j < 4; j++)   // LDS.64, conflict-free
                bv[j] = *reinterpret_cast<const ull*>(Bs + k * BS_STRIDE + 2 * cg + 64 * j);
#pragma unroll
            for (int i = 0; i < 8; i++)   // broadcast LDS.32 + splat
                av[i] = splat2(As[(rg * 8 + i) * KC + k]);
#pragma unroll
            for (int i = 0; i < 8; i++)
#pragma unroll
                for (int j = 0; j < 4; j++)
                    fma2(acc[i][j], av[i], bv[j]);
        }
        __syncthreads();
    }

    // ============ bias + LayerNorm (warp-local) + exact GELU ==============
    {
        float2 b1c[4], gm[4], bt[4];
#pragma unroll
        for (int j = 0; j < 4; j++) {
            int c = 2 * cg + 64 * j;
            b1c[j] = *reinterpret_cast<const float2*>(b1    + t * HD + c);
            gm[j]  = *reinterpret_cast<const float2*>(gamma + t * HD + c);
            bt[j]  = *reinterpret_cast<const float2*>(beta  + t * HD + c);
        }
#pragma unroll
        for (int i = 0; i < 8; i++) {
            float x[8];
            float s = 0.f, s2 = 0.f;
#pragma unroll
            for (int j = 0; j < 4; j++) {
                float2 f = unpack2(acc[i][j]);
                float x0 = f.x + b1c[j].x;
                float x1 = f.y + b1c[j].y;
                x[2 * j] = x0; x[2 * j + 1] = x1;
                s += x0 + x1;
                s2 = fmaf(x0, x0, s2);
                s2 = fmaf(x1, x1, s2);
            }
#pragma unroll
            for (int off = 16; off > 0; off >>= 1) {
                s  += __shfl_xor_sync(0xffffffffu, s, off);
                s2 += __shfl_xor_sync(0xffffffffu, s2, off);
            }
            float mu   = s * (1.f / HD);
            float var  = s2 * (1.f / HD) - mu * mu;
            float rstd = rsqrtf(var + 1e-5f);
            int r = rg * 8 + i;
#pragma unroll
            for (int j = 0; j < 4; j++) {
                float y0 = (x[2 * j]     - mu) * rstd * gm[j].x + bt[j].x;
                float y1 = (x[2 * j + 1] - mu) * rstd * gm[j].y + bt[j].y;
                float g0 = 0.5f * y0 * (1.f + erff(y0 * 0.70710678118654752f));
                float g1 = 0.5f * y1 * (1.f + erff(y1 * 0.70710678118654752f));
                *reinterpret_cast<float2*>(Hs + r * HD + 2 * cg + 64 * j) =
                    make_float2(g0, g1);   // STS.64, conflict-free
            }
        }
    }
    __syncthreads();

    // ========= GEMM2 (VD in two 256-col tiles) + cosine fold ==============
    float num[8], sq[8];
#pragma unroll
    for (int i = 0; i < 8; i++) { num[i] = 0.f; sq[i] = 0.f; }

    const float* W2t = W2 + (size_t)t * VD * HD;

#pragma unroll 1
    for (int nt = 0; nt < 2; nt++) {
        const int nbase = nt * 256;
        ull acc2[8][4];
#pragma unroll
        for (int i = 0; i < 8; i++)
#pragma unroll
            for (int j = 0; j < 4; j++) acc2[i][j] = 0ull;

        for (int k0 = 0; k0 < HD; k0 += KC) {
            // stage W2 tile transposed: Bs[k][nl], OOB cols -> 0
#pragma unroll
            for (int q = tid; q < 256 * (KC / 4); q += 256) {
                int nl = q >> 3, kq = q & 7;
                int n = nbase + nl;
                float4 v = make_float4(0.f, 0.f, 0.f, 0.f);
                if (n < VD)
                    v = *reinterpret_cast<const float4*>(W2t + (size_t)n * HD + k0 + kq * 4);
                int k = kq * 4;
                Bs[(k + 0) * BS_STRIDE + nl] = v.x;
                Bs[(k + 1) * BS_STRIDE + nl] = v.y;
                Bs[(k + 2) * BS_STRIDE + nl] = v.z;
                Bs[(k + 3) * BS_STRIDE + nl] = v.w;
            }
            __syncthreads();
#pragma unroll 8
            for (int k = 0; k < KC; k++) {
                ull bv[4], av[8];
#pragma unroll
                for (int j = 0; j < 4; j++)
                    bv[j] = *reinterpret_cast<const ull*>(Bs + k * BS_STRIDE + 2 * cg + 64 * j);
#pragma unroll
                for (int i = 0; i < 8; i++)
                    av[i] = splat2(Hs[(rg * 8 + i) * HD + k0 + k]);   // broadcast
#pragma unroll
                for (int i = 0; i < 8; i++)
#pragma unroll
                    for (int j = 0; j < 4; j++)
                        fma2(acc2[i][j], av[i], bv[j]);
            }
            __syncthreads();
        }
        // fold v = acc2 + b2 into cosine numerator and ||v||^2 (v never stored)
        // VD=484 is even and pair bases are even -> pairs are all-in or all-out.
#pragma unroll
        for (int j = 0; j < 4; j++) {
            int n0 = nbase + 2 * cg + 64 * j;
            if (n0 < VD) {
                float2 bb = *reinterpret_cast<const float2*>(b2   + (size_t)t * VD + n0);
                float2 cc = *reinterpret_cast<const float2*>(cent + (size_t)t * VD + n0);
#pragma unroll
                for (int i = 0; i < 8; i++) {
                    float2 f = unpack2(acc2[i][j]);
                    float v0 = f.x + bb.x;
                    float v1 = f.y + bb.y;
                    num[i] = fmaf(v0, cc.x, num[i]);
                    num[i] = fmaf(v1, cc.y, num[i]);
                    sq[i]  = fmaf(v0, v0, sq[i]);
                    sq[i]  = fmaf(v1, v1, sq[i]);
                }
            }
        }
    }

    // ================= per-row cosine, block partial =======================
    float cn = g_cnorm[t];
    float rowsum = 0.f;
#pragma unroll
    for (int i = 0; i < 8; i++) {
        float nu = num[i], s = sq[i];
#pragma unroll
        for (int off = 16; off > 0; off >>= 1) {
            nu += __shfl_xor_sync(0xffffffffu, nu, off);
            s  += __shfl_xor_sync(0xffffffffu, s, off);
        }
        float vn = fmaxf(sqrtf(s), 1e-8f);
        rowsum += 1.f - nu / (vn * cn);
    }
    if (cg == 0) red[rg] = rowsum;
    __syncthreads();
    if (tid == 0) {
        float bs = 0.f;
#pragma unroll
        for (int w = 0; w < 8; w++) bs += red[w];
        g_partial[t * NBLK + blockIdx.x] = bs;   // deterministic slot write, no atomics
    }
}

// ---------------------------------------------------------------------------
// Kernel 2: finalize -> distances[T] (mean over B) + argmin
// ---------------------------------------------------------------------------
__global__ void finalize_kernel(float* __restrict__ out, int out_size) {
    __shared__ float dist[T_TASKS];
    int t = threadIdx.x;
    if (t < T_TASKS) {
        float s = 0.f;
#pragma unroll
        for (int b = 0; b < NBLK; b++) s += g_partial[t * NBLK + b];
        float d = s * (1.0f / (float)B_ROWS);
        dist[t] = d;
        if (out_size >= T_TASKS) out[t] = d;
    }
    __syncthreads();
    if (t == 0) {
        int best = 0;
        float bv = dist[0];
        for (int i = 1; i < T_TASKS; i++)
            if (dist[i] < bv) { bv = dist[i]; best = i; }   // first-min tie-break (jnp.argmin)
        if (out_size >= T_TASKS + 1)      out[T_TASKS] = (float)best;
        else if (out_size >= 1 && out_size < T_TASKS) out[0] = (float)best;
    }
}

// ---------------------------------------------------------------------------
extern "C" void kernel_launch(void* const* d_in, const int* in_sizes, int n_in,
                              void* d_out, int out_size) {
    const float* t_feat = (const float*)d_in[0];
    const float* W1     = (const float*)d_in[1];
    const float* b1     = (const float*)d_in[2];
    const float* gamma  = (const float*)d_in[3];
    const float* beta   = (const float*)d_in[4];
    const float* W2     = (const float*)d_in[5];
    const float* b2     = (const float*)d_in[6];
    const float* cent   = (const float*)d_in[7];

    cudaFuncSetAttribute(router_kernel,
                         cudaFuncAttributeMaxDynamicSharedMemorySize, SMEM_BYTES);

    init_cnorm_kernel<<<T_TASKS, 128>>>(cent);
    dim3 grid(NBLK, T_TASKS);
    router_kernel<<<grid, 256, SMEM_BYTES>>>(t_feat, W1, b1, gamma, beta, W2, b2, cent);
    finalize_kernel<<<1, 64>>>((float*)d_out, out_size);
}

// round 8
// speedup vs baseline: 3.3275x; 1.8327x over previous
#include <cuda_runtime.h>
#include <cuda_bf16.h>
#include <math.h>
#include <stdint.h>

#define T_TASKS 64
#define B_ROWS  4096
#define TD      512
#define HD      256
#define VD      484
#define VDP     512
#define BM      128
#define NBLK    (B_ROWS / BM)   // 32

// ---- smem byte offsets ----
// low region
#define OFF_RED 0        // 544 floats (num/sq/stat reds + warp partials)
#define OFF_B1  2176
#define OFF_GM  3200
#define OFF_BT  4224
#define OFF_B2  5248     // 484 f
#define OFF_CT  7200     // 484 f, ends 9136
// GEMM1 staging (row stride 144 B for [.,64] bf16 tiles)
#define SA_HI   16384    // 128*144 = 18432
#define SA_LO   34816
#define SB_HI   53248    // 256*144 = 36864
#define SB_LO   90112    // ends 126976
// H (post-GELU, hi/lo bf16 [128][256], row stride 528 B) — overlaps GEMM1 staging
#define HS_HI   16384    // 128*528 = 67584
#define HS_LO   83968    // ends 151552
// GEMM2 W2 staging
#define W2H     151552   // 18432
#define W2L     169984   // ends 188416
#define SMEM_BYTES 188416

// ---- precomputed bf16 hi/lo operands ----
#define TF_PAIRS  ((size_t)B_ROWS * TD / 2)
#define W1_PAIRS  ((size_t)T_TASKS * HD * TD / 2)
#define W2_PAIRS  ((size_t)T_TASKS * VDP * HD / 2)
#define CVT_TOTAL (TF_PAIRS + W1_PAIRS + W2_PAIRS)
__device__ uint4 g_tf_h[TF_PAIRS / 4];
__device__ uint4 g_tf_l[TF_PAIRS / 4];
__device__ uint4 g_w1_h[W1_PAIRS / 4];
__device__ uint4 g_w1_l[W1_PAIRS / 4];
__device__ uint4 g_w2_h[W2_PAIRS / 4];
__device__ uint4 g_w2_l[W2_PAIRS / 4];
__device__ float g_partial[T_TASKS * NBLK];
__device__ float g_cnorm[T_TASKS];

__device__ __forceinline__ uint32_t smem_u32(const void* p) {
    uint32_t a;
    asm("{ .reg .u64 t; cvta.to.shared.u64 t, %1; cvt.u32.u64 %0, t; }" : "=r"(a) : "l"(p));
    return a;
}
__device__ __forceinline__ void ldsm4(uint32_t* r, uint32_t addr) {
    asm volatile("ldmatrix.sync.aligned.m8n8.x4.shared.b16 {%0,%1,%2,%3}, [%4];"
        : "=r"(r[0]), "=r"(r[1]), "=r"(r[2]), "=r"(r[3]) : "r"(addr));
}
__device__ __forceinline__ void mma16816(float* d, const uint32_t* a, const uint32_t* b) {
    asm volatile("mma.sync.aligned.m16n8k16.row.col.f32.bf16.bf16.f32 "
        "{%0,%1,%2,%3}, {%4,%5,%6,%7}, {%8,%9}, {%0,%1,%2,%3};"
        : "+f"(d[0]), "+f"(d[1]), "+f"(d[2]), "+f"(d[3])
        : "r"(a[0]), "r"(a[1]), "r"(a[2]), "r"(a[3]), "r"(b[0]), "r"(b[1]));
}

// ---------------------------------------------------------------------------
// convert fp32 -> bf16 hi/lo pairs (W2 padded to VDP rows)
// ---------------------------------------------------------------------------
__global__ void convert_kernel(const float* __restrict__ tf,
                               const float* __restrict__ W1,
                               const float* __restrict__ W2) {
    size_t p = (size_t)blockIdx.x * blockDim.x + threadIdx.x;
    if (p >= CVT_TOTAL) return;
    float x0, x1; unsigned *hi, *lo; size_t idx;
    if (p < TF_PAIRS) {
        idx = p; x0 = tf[2 * p]; x1 = tf[2 * p + 1];
        hi = (unsigned*)g_tf_h; lo = (unsigned*)g_tf_l;
    } else if (p < TF_PAIRS + W1_PAIRS) {
        idx = p - TF_PAIRS; x0 = W1[2 * idx]; x1 = W1[2 * idx + 1];
        hi = (unsigned*)g_w1_h; lo = (unsigned*)g_w1_l;
    } else {
        idx = p - TF_PAIRS - W1_PAIRS;
        size_t per_task = (size_t)VDP * HD / 2;
        size_t t = idx / per_task, r = idx % per_task;
        size_t n = r / (HD / 2), k2 = r % (HD / 2);
        if (n < VD) {
            const float* s = W2 + t * (size_t)VD * HD + n * HD + 2 * k2;
            x0 = s[0]; x1 = s[1];
        } else { x0 = 0.f; x1 = 0.f; }
        hi = (unsigned*)g_w2_h; lo = (unsigned*)g_w2_l;
    }
    __nv_bfloat16 h0 = __float2bfloat16(x0), h1 = __float2bfloat16(x1);
    __nv_bfloat16 l0 = __float2bfloat16(x0 - __bfloat162float(h0));
    __nv_bfloat16 l1 = __float2bfloat16(x1 - __bfloat162float(h1));
    hi[idx] = ((unsigned)__bfloat16_as_ushort(h1) << 16) | __bfloat16_as_ushort(h0);
    lo[idx] = ((unsigned)__bfloat16_as_ushort(l1) << 16) | __bfloat16_as_ushort(l0);
}

__global__ void init_cnorm_kernel(const float* __restrict__ cent) {
    int t = blockIdx.x;
    float s = 0.f;
    for (int n = threadIdx.x; n < VD; n += 128) {
        float c = cent[t * VD + n];
        s = fmaf(c, c, s);
    }
#pragma unroll
    for (int o = 16; o > 0; o >>= 1) s += __shfl_xor_sync(0xffffffffu, s, o);
    __shared__ float ws[4];
    if ((threadIdx.x & 31) == 0) ws[threadIdx.x >> 5] = s;
    __syncthreads();
    if (threadIdx.x == 0) g_cnorm[t] = fmaxf(sqrtf(ws[0] + ws[1] + ws[2] + ws[3]), 1e-8f);
}

// ---------------------------------------------------------------------------
// fused HMMA router: block=(mtile, task), 256 threads = warp grid 4(rows)x2(cols)
// warp tile 32x64; GEMM1 loops 2 N-halves (N=256); GEMM2 loops 4 N-tiles (VDP).
// ---------------------------------------------------------------------------
__global__ __launch_bounds__(256, 1)
void router_mma(const float* __restrict__ b1v, const float* __restrict__ gamma,
                const float* __restrict__ beta, const float* __restrict__ b2v,
                const float* __restrict__ cent) {
    extern __shared__ char smem[];
    const uint32_t sbase = smem_u32(smem);
    const int tid = threadIdx.x;
    const int w = tid >> 5, l = tid & 31;
    const int wr = w & 3, wc = w >> 2;      // row-group (4), col-group (2)
    const int m0 = wr * 32;
    const int g  = l >> 2, q4 = l & 3;      // quad row, quad lane
    const int t = blockIdx.y;
    const int brow0 = blockIdx.x * BM;

    float* red = (float*)(smem + OFF_RED);
    float* b1s = (float*)(smem + OFF_B1);
    float* gms = (float*)(smem + OFF_GM);
    float* bts = (float*)(smem + OFF_BT);
    float* b2s = (float*)(smem + OFF_B2);
    float* cts = (float*)(smem + OFF_CT);

    if (tid < HD) {
        b1s[tid] = b1v[t * HD + tid];
        gms[tid] = gamma[t * HD + tid];
        bts[tid] = beta[t * HD + tid];
    }
    for (int i = tid; i < VD; i += 256) {
        b2s[i] = b2v[(size_t)t * VD + i];
        cts[i] = cent[(size_t)t * VD + i];
    }

    // per-lane ldmatrix address components
    const int a_mrow = ((l >> 3) & 1) * 8 + (l & 7);   // A: row-half from bit3
    const int a_kh   = (l >> 4) * 16;                   // A: k-half (bytes) from bit4
    const int b_nrow = (l >> 4) * 8 + (l & 7);          // B: row-half from bit4
    const int b_kh   = ((l >> 3) & 1) * 16;             // B: k-half (bytes) from bit3

    // ===================== GEMM1: acc[2 halves][2 mi][8 ni][4] =============
    float acc[2][2][8][4];
#pragma unroll
    for (int h = 0; h < 2; h++)
#pragma unroll
        for (int mi = 0; mi < 2; mi++)
#pragma unroll
            for (int ni = 0; ni < 8; ni++)
#pragma unroll
                for (int e = 0; e < 4; e++) acc[h][mi][ni][e] = 0.f;

    for (int c = 0; c < 8; c++) {
        // stage A [128x64] hi/lo
        for (int q = tid; q < 1024; q += 256) {
            int r = q >> 3, i = q & 7;
            size_t gi = (size_t)(brow0 + r) * 64 + (size_t)c * 8 + i;
            int off = r * 144 + i * 16;
            *(uint4*)(smem + SA_HI + off) = g_tf_h[gi];
            *(uint4*)(smem + SA_LO + off) = g_tf_l[gi];
        }
        // stage B = W1 [256x64] hi/lo
        for (int q = tid; q < 2048; q += 256) {
            int n = q >> 3, i = q & 7;
            size_t gi = (size_t)t * 16384 + (size_t)n * 64 + (size_t)c * 8 + i;
            int off = n * 144 + i * 16;
            *(uint4*)(smem + SB_HI + off) = g_w1_h[gi];
            *(uint4*)(smem + SB_LO + off) = g_w1_l[gi];
        }
        __syncthreads();
#pragma unroll
        for (int kk = 0; kk < 4; kk++) {
            const int kb = kk * 32;
            uint32_t ah[2][4], al[2][4];
#pragma unroll
            for (int mi = 0; mi < 2; mi++) {
                int ro = (m0 + mi * 16 + a_mrow) * 144 + kb + a_kh;
                ldsm4(ah[mi], sbase + SA_HI + ro);
                ldsm4(al[mi], sbase + SA_LO + ro);
            }
#pragma unroll
            for (int h = 0; h < 2; h++) {
#pragma unroll
                for (int p = 0; p < 4; p++) {
                    int nb = h * 128 + wc * 64 + p * 16;
                    int ro = (nb + b_nrow) * 144 + kb + b_kh;
                    uint32_t bh[4], bl[4];
                    ldsm4(bh, sbase + SB_HI + ro);
                    ldsm4(bl, sbase + SB_LO + ro);
#pragma unroll
                    for (int mi = 0; mi < 2; mi++)
#pragma unroll
                        for (int e = 0; e < 2; e++) {
                            float* C = acc[h][mi][p * 2 + e];
                            mma16816(C, ah[mi], bh + e * 2);
                            mma16816(C, ah[mi], bl + e * 2);
                            mma16816(C, al[mi], bh + e * 2);
                        }
                }
            }
        }
        __syncthreads();
    }

    // ======= epilogue 1: bias + LayerNorm + GELU -> H hi/lo smem ===========
    {
        float s[4] = {0, 0, 0, 0}, s2[4] = {0, 0, 0, 0};
#pragma unroll
        for (int h = 0; h < 2; h++)
#pragma unroll
            for (int mi = 0; mi < 2; mi++)
#pragma unroll
                for (int ni = 0; ni < 8; ni++) {
                    int col = h * 128 + wc * 64 + ni * 8 + q4 * 2;
                    float bb0 = b1s[col], bb1 = b1s[col + 1];
                    float* C = acc[h][mi][ni];
                    C[0] += bb0; C[1] += bb1; C[2] += bb0; C[3] += bb1;
                    s[mi * 2 + 0] += C[0] + C[1];
                    s2[mi * 2 + 0] = fmaf(C[0], C[0], fmaf(C[1], C[1], s2[mi * 2 + 0]));
                    s[mi * 2 + 1] += C[2] + C[3];
                    s2[mi * 2 + 1] = fmaf(C[2], C[2], fmaf(C[3], C[3], s2[mi * 2 + 1]));
                }
#pragma unroll
        for (int sl = 0; sl < 4; sl++)
#pragma unroll
            for (int o = 1; o < 4; o <<= 1) {
                s[sl]  += __shfl_xor_sync(0xffffffffu, s[sl], o);
                s2[sl] += __shfl_xor_sync(0xffffffffu, s2[sl], o);
            }
        if (q4 == 0) {
#pragma unroll
            for (int sl = 0; sl < 4; sl++) {
                int r = m0 + (sl >> 1) * 16 + (sl & 1) * 8 + g;
                red[wc * 128 + r] = s[sl];
                red[256 + wc * 128 + r] = s2[sl];
            }
        }
        __syncthreads();
        float mu[4], rs[4];
#pragma unroll
        for (int sl = 0; sl < 4; sl++) {
            int r = m0 + (sl >> 1) * 16 + (sl & 1) * 8 + g;
            float ts  = red[r] + red[128 + r];
            float ts2 = red[256 + r] + red[384 + r];
            mu[sl] = ts * (1.f / HD);
            rs[sl] = rsqrtf(ts2 * (1.f / HD) - mu[sl] * mu[sl] + 1e-5f);
        }
        __syncthreads();   // red free for reuse after this
#pragma unroll
        for (int h = 0; h < 2; h++)
#pragma unroll
            for (int mi = 0; mi < 2; mi++)
#pragma unroll
                for (int ni = 0; ni < 8; ni++) {
                    int col = h * 128 + wc * 64 + ni * 8 + q4 * 2;
                    float gm0 = gms[col], gm1 = gms[col + 1];
                    float bt0 = bts[col], bt1 = bts[col + 1];
                    float* C = acc[h][mi][ni];
#pragma unroll
                    for (int rh = 0; rh < 2; rh++) {
                        int sl = mi * 2 + rh;
                        int r = m0 + mi * 16 + rh * 8 + g;
                        float y0 = (C[rh * 2 + 0] - mu[sl]) * rs[sl] * gm0 + bt0;
                        float y1 = (C[rh * 2 + 1] - mu[sl]) * rs[sl] * gm1 + bt1;
                        float g0 = 0.5f * y0 * (1.f + erff(y0 * 0.70710678118654752f));
                        float g1 = 0.5f * y1 * (1.f + erff(y1 * 0.70710678118654752f));
                        __nv_bfloat16 h0 = __float2bfloat16(g0), h1 = __float2bfloat16(g1);
                        __nv_bfloat16 l0 = __float2bfloat16(g0 - __bfloat162float(h0));
                        __nv_bfloat16 l1 = __float2bfloat16(g1 - __bfloat162float(h1));
                        *(unsigned*)(smem + HS_HI + r * 528 + col * 2) =
                            ((unsigned)__bfloat16_as_ushort(h1) << 16) | __bfloat16_as_ushort(h0);
                        *(unsigned*)(smem + HS_LO + r * 528 + col * 2) =
                            ((unsigned)__bfloat16_as_ushort(l1) << 16) | __bfloat16_as_ushort(l0);
                    }
                }
    }
    __syncthreads();

    // ===== GEMM2: 4 N-tiles x 128 (VDP), K=256 in 4 chunks; cosine fold ====
    float num[4] = {0, 0, 0, 0}, sq[4] = {0, 0, 0, 0};
    for (int nt = 0; nt < 4; nt++) {
        float acc2[2][8][4];
#pragma unroll
        for (int mi = 0; mi < 2; mi++)
#pragma unroll
            for (int ni = 0; ni < 8; ni++)
#pragma unroll
                for (int e = 0; e < 4; e++) acc2[mi][ni][e] = 0.f;

        for (int c = 0; c < 4; c++) {
            for (int q = tid; q < 1024; q += 256) {
                int r = q >> 3, i = q & 7;
                size_t gi = (size_t)t * 16384 + (size_t)(nt * 128 + r) * 32 + (size_t)c * 8 + i;
                int off = r * 144 + i * 16;
                *(uint4*)(smem + W2H + off) = g_w2_h[gi];
                *(uint4*)(smem + W2L + off) = g_w2_l[gi];
            }
            __syncthreads();
#pragma unroll
            for (int kk = 0; kk < 4; kk++) {
                const int kb = kk * 32;
                uint32_t ah[2][4], al[2][4];
#pragma unroll
                for (int mi = 0; mi < 2; mi++) {
                    int ro = (m0 + mi * 16 + a_mrow) * 528 + c * 128 + kb + a_kh;
                    ldsm4(ah[mi], sbase + HS_HI + ro);
                    ldsm4(al[mi], sbase + HS_LO + ro);
                }
#pragma unroll
                for (int p = 0; p < 4; p++) {
                    int ro = (wc * 64 + p * 16 + b_nrow) * 144 + kb + b_kh;
                    uint32_t bh[4], bl[4];
                    ldsm4(bh, sbase + W2H + ro);
                    ldsm4(bl, sbase + W2L + ro);
#pragma unroll
                    for (int mi = 0; mi < 2; mi++)
#pragma unroll
                        for (int e = 0; e < 2; e++) {
                            float* C = acc2[mi][p * 2 + e];
                            mma16816(C, ah[mi], bh + e * 2);
                            mma16816(C, ah[mi], bl + e * 2);
                            mma16816(C, al[mi], bh + e * 2);
                        }
                }
            }
            __syncthreads();
        }
        // fold v = acc2 + b2 into cosine sums (cols even; VD even -> pairwise)
#pragma unroll
        for (int mi = 0; mi < 2; mi++)
#pragma unroll
            for (int ni = 0; ni < 8; ni++) {
                int col = nt * 128 + wc * 64 + ni * 8 + q4 * 2;
                if (col < VD) {
                    float bb0 = b2s[col], bb1 = b2s[col + 1];
                    float cc0 = cts[col], cc1 = cts[col + 1];
                    float* C = acc2[mi][ni];
#pragma unroll
                    for (int rh = 0; rh < 2; rh++) {
                        int sl = mi * 2 + rh;
                        float v0 = C[rh * 2 + 0] + bb0;
                        float v1 = C[rh * 2 + 1] + bb1;
                        num[sl] = fmaf(v0, cc0, fmaf(v1, cc1, num[sl]));
                        sq[sl]  = fmaf(v0, v0, fmaf(v1, v1, sq[sl]));
                    }
                }
            }
    }

    // ================= per-row cosine, block partial =======================
#pragma unroll
    for (int sl = 0; sl < 4; sl++)
#pragma unroll
        for (int o = 1; o < 4; o <<= 1) {
            num[sl] += __shfl_xor_sync(0xffffffffu, num[sl], o);
            sq[sl]  += __shfl_xor_sync(0xffffffffu, sq[sl], o);
        }
    if (q4 == 0) {
#pragma unroll
        for (int sl = 0; sl < 4; sl++) {
            int r = m0 + (sl >> 1) * 16 + (sl & 1) * 8 + g;
            red[wc * 128 + r] = num[sl];
            red[256 + wc * 128 + r] = sq[sl];
        }
    }
    __syncthreads();
    float rd = 0.f;
    if (wc == 0 && q4 == 0) {
        float cn = g_cnorm[t];
#pragma unroll
        for (int sl = 0; sl < 4; sl++) {
            int r = m0 + (sl >> 1) * 16 + (sl & 1) * 8 + g;
            float nu = red[r] + red[128 + r];
            float sv = red[256 + r] + red[384 + r];
            float vn = fmaxf(sqrtf(sv), 1e-8f);
            rd += 1.f - nu / (vn * cn);
        }
    }
#pragma unroll
    for (int o = 16; o > 0; o >>= 1) rd += __shfl_xor_sync(0xffffffffu, rd, o);
    if (wc == 0 && l == 0) red[512 + wr] = rd;
    __syncthreads();
    if (tid == 0)
        g_partial[t * NBLK + blockIdx.x] = red[512] + red[513] + red[514] + red[515];
}

__global__ void finalize_kernel(float* __restrict__ out, int out_size) {
    __shared__ float dist[T_TASKS];
    int t = threadIdx.x;
    if (t < T_TASKS) {
        float s = 0.f;
#pragma unroll
        for (int b = 0; b < NBLK; b++) s += g_partial[t * NBLK + b];
        float d = s * (1.0f / (float)B_ROWS);
        dist[t] = d;
        if (out_size >= T_TASKS) out[t] = d;
    }
    __syncthreads();
    if (t == 0) {
        int best = 0; float bv = dist[0];
        for (int i = 1; i < T_TASKS; i++)
            if (dist[i] < bv) { bv = dist[i]; best = i; }
        if (out_size >= T_TASKS + 1)      out[T_TASKS] = (float)best;
        else if (out_size >= 1 && out_size < T_TASKS) out[0] = (float)best;
    }
}

extern "C" void kernel_launch(void* const* d_in, const int* in_sizes, int n_in,
                              void* d_out, int out_size) {
    const float* t_feat = (const float*)d_in[0];
    const float* W1     = (const float*)d_in[1];
    const float* b1     = (const float*)d_in[2];
    const float* gamma  = (const float*)d_in[3];
    const float* beta   = (const float*)d_in[4];
    const float* W2     = (const float*)d_in[5];
    const float* b2     = (const float*)d_in[6];
    const float* cent   = (const float*)d_in[7];

    cudaFuncSetAttribute(router_mma, cudaFuncAttributeMaxDynamicSharedMemorySize, SMEM_BYTES);

    int cvt_blocks = (int)((CVT_TOTAL + 255) / 256);
    convert_kernel<<<cvt_blocks, 256>>>(t_feat, W1, W2);
    init_cnorm_kernel<<<T_TASKS, 128>>>(cent);
    dim3 grid(NBLK, T_TASKS);
    router_mma<<<grid, 256, SMEM_BYTES>>>(b1, gamma, beta, b2, cent);
    finalize_kernel<<<1, 64>>>((float*)d_out, out_size);
}

// round 10
// speedup vs baseline: 4.4057x; 1.3240x over previous
#include <cuda_runtime.h>
#include <cuda_bf16.h>
#include <math.h>
#include <stdint.h>

#define T_TASKS 64
#define B_ROWS  4096
#define TD      512
#define HD      256
#define VD      484
#define VDP     512
#define BM      128
#define NBLK    (B_ROWS / BM)   // 32

// ---- smem byte offsets ----
#define OFF_RED 0        // 544 floats
#define OFF_B1  2176
#define OFF_GM  3200
#define OFF_BT  4224
#define OFF_B2  5248
#define OFF_CT  7200     // ends 9136
// GEMM1 staging: KC=32, row stride 80 B, double buffered.
// per buffer: A_hi 128*80=10240, A_lo 10240, B_hi 256*80=20480, B_lo 20480
#define G1_BUF(b) (9216 + (b) * 61440)     // ends 132096
#define G1_AH 0
#define G1_AL 10240
#define G1_BH 20480
#define G1_BL 40960
// H (post-GELU hi/lo bf16 [128][256], row stride 528 B) — reuses GEMM1 region
#define HS_HI 9216       // 128*528 = 67584
#define HS_LO 76800      // ends 144384
// GEMM2 W2 staging: KC=64, row stride 144 B, double buffered (hi+lo per buffer)
#define W2_BUF(b) (144384 + (b) * 36864)   // ends 218112
#define W2H 0
#define W2L 18432
#define SMEM_BYTES 218112

// ---- precomputed bf16 hi/lo operands ----
#define TF_PAIRS  ((size_t)B_ROWS * TD / 2)
#define W1_PAIRS  ((size_t)T_TASKS * HD * TD / 2)
#define W2_PAIRS  ((size_t)T_TASKS * VDP * HD / 2)
#define CVT_TOTAL (TF_PAIRS + W1_PAIRS + W2_PAIRS)
__device__ uint4 g_tf_h[TF_PAIRS / 4];
__device__ uint4 g_tf_l[TF_PAIRS / 4];
__device__ uint4 g_w1_h[W1_PAIRS / 4];
__device__ uint4 g_w1_l[W1_PAIRS / 4];
__device__ uint4 g_w2_h[W2_PAIRS / 4];
__device__ uint4 g_w2_l[W2_PAIRS / 4];
__device__ float g_partial[T_TASKS * NBLK];
__device__ float g_cnorm[T_TASKS];

__device__ __forceinline__ uint32_t smem_u32(const void* p) {
    uint32_t a;
    asm("{ .reg .u64 t; cvta.to.shared.u64 t, %1; cvt.u32.u64 %0, t; }" : "=r"(a) : "l"(p));
    return a;
}
__device__ __forceinline__ void ldsm4(uint32_t* r, uint32_t addr) {
    asm volatile("ldmatrix.sync.aligned.m8n8.x4.shared.b16 {%0,%1,%2,%3}, [%4];"
        : "=r"(r[0]), "=r"(r[1]), "=r"(r[2]), "=r"(r[3]) : "r"(addr));
}
__device__ __forceinline__ void mma16816(float* d, const uint32_t* a, const uint32_t* b) {
    asm volatile("mma.sync.aligned.m16n8k16.row.col.f32.bf16.bf16.f32 "
        "{%0,%1,%2,%3}, {%4,%5,%6,%7}, {%8,%9}, {%0,%1,%2,%3};"
        : "+f"(d[0]), "+f"(d[1]), "+f"(d[2]), "+f"(d[3])
        : "r"(a[0]), "r"(a[1]), "r"(a[2]), "r"(a[3]), "r"(b[0]), "r"(b[1]));
}
__device__ __forceinline__ void cpa16(uint32_t dst, const void* src) {
    asm volatile("cp.async.cg.shared.global [%0], [%1], 16;" :: "r"(dst), "l"(src));
}
#define CP_COMMIT() asm volatile("cp.async.commit_group;" ::: "memory")
#define CP_WAIT0()  asm volatile("cp.async.wait_group 0;" ::: "memory")
#define CP_WAIT1()  asm volatile("cp.async.wait_group 1;" ::: "memory")

// ---------------------------------------------------------------------------
// convert fp32 -> bf16 hi/lo pairs (W2 padded to VDP rows)
// ---------------------------------------------------------------------------
__global__ void convert_kernel(const float* __restrict__ tf,
                               const float* __restrict__ W1,
                               const float* __restrict__ W2) {
    size_t p = (size_t)blockIdx.x * blockDim.x + threadIdx.x;
    if (p >= CVT_TOTAL) return;
    float x0, x1; unsigned *hi, *lo; size_t idx;
    if (p < TF_PAIRS) {
        idx = p; x0 = tf[2 * p]; x1 = tf[2 * p + 1];
        hi = (unsigned*)g_tf_h; lo = (unsigned*)g_tf_l;
    } else if (p < TF_PAIRS + W1_PAIRS) {
        idx = p - TF_PAIRS; x0 = W1[2 * idx]; x1 = W1[2 * idx + 1];
        hi = (unsigned*)g_w1_h; lo = (unsigned*)g_w1_l;
    } else {
        idx = p - TF_PAIRS - W1_PAIRS;
        size_t per_task = (size_t)VDP * HD / 2;
        size_t t = idx / per_task, r = idx % per_task;
        size_t n = r / (HD / 2), k2 = r % (HD / 2);
        if (n < VD) {
            const float* s = W2 + t * (size_t)VD * HD + n * HD + 2 * k2;
            x0 = s[0]; x1 = s[1];
        } else { x0 = 0.f; x1 = 0.f; }
        hi = (unsigned*)g_w2_h; lo = (unsigned*)g_w2_l;
    }
    __nv_bfloat16 h0 = __float2bfloat16(x0), h1 = __float2bfloat16(x1);
    __nv_bfloat16 l0 = __float2bfloat16(x0 - __bfloat162float(h0));
    __nv_bfloat16 l1 = __float2bfloat16(x1 - __bfloat162float(h1));
    hi[idx] = ((unsigned)__bfloat16_as_ushort(h1) << 16) | __bfloat16_as_ushort(h0);
    lo[idx] = ((unsigned)__bfloat16_as_ushort(l1) << 16) | __bfloat16_as_ushort(l0);
}

__global__ void init_cnorm_kernel(const float* __restrict__ cent) {
    int t = blockIdx.x;
    float s = 0.f;
    for (int n = threadIdx.x; n < VD; n += 128) {
        float c = cent[t * VD + n];
        s = fmaf(c, c, s);
    }
#pragma unroll
    for (int o = 16; o > 0; o >>= 1) s += __shfl_xor_sync(0xffffffffu, s, o);
    __shared__ float ws[4];
    if ((threadIdx.x & 31) == 0) ws[threadIdx.x >> 5] = s;
    __syncthreads();
    if (threadIdx.x == 0) g_cnorm[t] = fmaxf(sqrtf(ws[0] + ws[1] + ws[2] + ws[3]), 1e-8f);
}

// ---------------------------------------------------------------------------
// fused HMMA router, cp.async double-buffered
// ---------------------------------------------------------------------------
__global__ __launch_bounds__(256, 1)
void router_mma(const float* __restrict__ b1v, const float* __restrict__ gamma,
                const float* __restrict__ beta, const float* __restrict__ b2v,
                const float* __restrict__ cent) {
    extern __shared__ char smem[];
    const uint32_t sbase = smem_u32(smem);
    const int tid = threadIdx.x;
    const int w = tid >> 5, l = tid & 31;
    const int wr = w & 3, wc = w >> 2;
    const int m0 = wr * 32;
    const int g  = l >> 2, q4 = l & 3;
    const int t = blockIdx.y;
    const int brow0 = blockIdx.x * BM;

    float* red = (float*)(smem + OFF_RED);
    float* b1s = (float*)(smem + OFF_B1);
    float* gms = (float*)(smem + OFF_GM);
    float* bts = (float*)(smem + OFF_BT);
    float* b2s = (float*)(smem + OFF_B2);
    float* cts = (float*)(smem + OFF_CT);

    if (tid < HD) {
        b1s[tid] = b1v[t * HD + tid];
        gms[tid] = gamma[t * HD + tid];
        bts[tid] = beta[t * HD + tid];
    }
    for (int i = tid; i < VD; i += 256) {
        b2s[i] = b2v[(size_t)t * VD + i];
        cts[i] = cent[(size_t)t * VD + i];
    }

    const int a_mrow = ((l >> 3) & 1) * 8 + (l & 7);
    const int a_kh   = (l >> 4) * 16;
    const int b_nrow = (l >> 4) * 8 + (l & 7);
    const int b_kh   = ((l >> 3) & 1) * 16;

    // ---- staging lambdas (cp.async) ----
    auto stage_g1 = [&](int c, int b) {
        uint32_t base = sbase + G1_BUF(b);
#pragma unroll
        for (int q = tid; q < 512; q += 256) {            // A: 128 rows x 4 uint4
            int r = q >> 2, i = q & 3;
            size_t gi = (size_t)(brow0 + r) * 64 + (size_t)c * 4 + i;
            int off = r * 80 + i * 16;
            cpa16(base + G1_AH + off, &g_tf_h[gi]);
            cpa16(base + G1_AL + off, &g_tf_l[gi]);
        }
#pragma unroll
        for (int q = tid; q < 1024; q += 256) {           // B=W1: 256 rows x 4 uint4
            int r = q >> 2, i = q & 3;
            size_t gi = (size_t)t * 16384 + (size_t)r * 64 + (size_t)c * 4 + i;
            int off = r * 80 + i * 16;
            cpa16(base + G1_BH + off, &g_w1_h[gi]);
            cpa16(base + G1_BL + off, &g_w1_l[gi]);
        }
    };
    auto stage_w2 = [&](int u, int b) {                   // u = nt*4 + c (KC=64)
        int nt = u >> 2, c = u & 3;
        uint32_t base = sbase + W2_BUF(b);
#pragma unroll
        for (int q = tid; q < 1024; q += 256) {           // FIXED: 128 rows x 8 uint4
            int r = q >> 3, i = q & 7;
            size_t gi = (size_t)t * 16384 + (size_t)(nt * 128 + r) * 32 + (size_t)c * 8 + i;
            int off = r * 144 + i * 16;
            cpa16(base + W2H + off, &g_w2_h[gi]);
            cpa16(base + W2L + off, &g_w2_l[gi]);
        }
    };

    // ===================== GEMM1 (16 chunks of KC=32) ======================
    float acc[2][2][8][4];
#pragma unroll
    for (int h = 0; h < 2; h++)
#pragma unroll
        for (int mi = 0; mi < 2; mi++)
#pragma unroll
            for (int ni = 0; ni < 8; ni++)
#pragma unroll
                for (int e = 0; e < 4; e++) acc[h][mi][ni][e] = 0.f;

    stage_g1(0, 0);
    CP_COMMIT();
    for (int c = 0; c < 16; c++) {
        const int b = c & 1;
        if (c < 15) { stage_g1(c + 1, b ^ 1); CP_COMMIT(); CP_WAIT1(); }
        else        { CP_WAIT0(); }
        __syncthreads();
        uint32_t abase = sbase + G1_BUF(b);
#pragma unroll
        for (int kk = 0; kk < 2; kk++) {
            const int kb = kk * 32;
            uint32_t ah[2][4], al[2][4];
#pragma unroll
            for (int mi = 0; mi < 2; mi++) {
                int ro = (m0 + mi * 16 + a_mrow) * 80 + kb + a_kh;
                ldsm4(ah[mi], abase + G1_AH + ro);
                ldsm4(al[mi], abase + G1_AL + ro);
            }
#pragma unroll
            for (int h = 0; h < 2; h++) {
#pragma unroll
                for (int p = 0; p < 4; p++) {
                    int ro = (h * 128 + wc * 64 + p * 16 + b_nrow) * 80 + kb + b_kh;
                    uint32_t bh[4], bl[4];
                    ldsm4(bh, abase + G1_BH + ro);
                    ldsm4(bl, abase + G1_BL + ro);
#pragma unroll
                    for (int mi = 0; mi < 2; mi++)
#pragma unroll
                        for (int e = 0; e < 2; e++) {
                            float* C = acc[h][mi][p * 2 + e];
                            mma16816(C, ah[mi], bh + e * 2);
                            mma16816(C, ah[mi], bl + e * 2);
                            mma16816(C, al[mi], bh + e * 2);
                        }
                }
            }
        }
        __syncthreads();
    }

    // prefetch first W2 chunk under the epilogue
    stage_w2(0, 0);
    CP_COMMIT();

    // ======= epilogue 1: bias + LayerNorm + GELU -> H hi/lo smem ===========
    {
        float s[4] = {0, 0, 0, 0}, s2[4] = {0, 0, 0, 0};
#pragma unroll
        for (int h = 0; h < 2; h++)
#pragma unroll
            for (int mi = 0; mi < 2; mi++)
#pragma unroll
                for (int ni = 0; ni < 8; ni++) {
                    int col = h * 128 + wc * 64 + ni * 8 + q4 * 2;
                    float bb0 = b1s[col], bb1 = b1s[col + 1];
                    float* C = acc[h][mi][ni];
                    C[0] += bb0; C[1] += bb1; C[2] += bb0; C[3] += bb1;
                    s[mi * 2 + 0] += C[0] + C[1];
                    s2[mi * 2 + 0] = fmaf(C[0], C[0], fmaf(C[1], C[1], s2[mi * 2 + 0]));
                    s[mi * 2 + 1] += C[2] + C[3];
                    s2[mi * 2 + 1] = fmaf(C[2], C[2], fmaf(C[3], C[3], s2[mi * 2 + 1]));
                }
#pragma unroll
        for (int sl = 0; sl < 4; sl++)
#pragma unroll
            for (int o = 1; o < 4; o <<= 1) {
                s[sl]  += __shfl_xor_sync(0xffffffffu, s[sl], o);
                s2[sl] += __shfl_xor_sync(0xffffffffu, s2[sl], o);
            }
        if (q4 == 0) {
#pragma unroll
            for (int sl = 0; sl < 4; sl++) {
                int r = m0 + (sl >> 1) * 16 + (sl & 1) * 8 + g;
                red[wc * 128 + r] = s[sl];
                red[256 + wc * 128 + r] = s2[sl];
            }
        }
        __syncthreads();
        float mu[4], rs[4];
#pragma unroll
        for (int sl = 0; sl < 4; sl++) {
            int r = m0 + (sl >> 1) * 16 + (sl & 1) * 8 + g;
            float ts  = red[r] + red[128 + r];
            float ts2 = red[256 + r] + red[384 + r];
            mu[sl] = ts * (1.f / HD);
            rs[sl] = rsqrtf(ts2 * (1.f / HD) - mu[sl] * mu[sl] + 1e-5f);
        }
        __syncthreads();
#pragma unroll
        for (int h = 0; h < 2; h++)
#pragma unroll
            for (int mi = 0; mi < 2; mi++)
#pragma unroll
                for (int ni = 0; ni < 8; ni++) {
                    int col = h * 128 + wc * 64 + ni * 8 + q4 * 2;
                    float gm0 = gms[col], gm1 = gms[col + 1];
                    float bt0 = bts[col], bt1 = bts[col + 1];
                    float* C = acc[h][mi][ni];
#pragma unroll
                    for (int rh = 0; rh < 2; rh++) {
                        int sl = mi * 2 + rh;
                        int r = m0 + mi * 16 + rh * 8 + g;
                        float y0 = (C[rh * 2 + 0] - mu[sl]) * rs[sl] * gm0 + bt0;
                        float y1 = (C[rh * 2 + 1] - mu[sl]) * rs[sl] * gm1 + bt1;
                        float g0 = 0.5f * y0 * (1.f + erff(y0 * 0.70710678118654752f));
                        float g1 = 0.5f * y1 * (1.f + erff(y1 * 0.70710678118654752f));
                        __nv_bfloat16 h0 = __float2bfloat16(g0), h1 = __float2bfloat16(g1);
                        __nv_bfloat16 l0 = __float2bfloat16(g0 - __bfloat162float(h0));
                        __nv_bfloat16 l1 = __float2bfloat16(g1 - __bfloat162float(h1));
                        *(unsigned*)(smem + HS_HI + r * 528 + col * 2) =
                            ((unsigned)__bfloat16_as_ushort(h1) << 16) | __bfloat16_as_ushort(h0);
                        *(unsigned*)(smem + HS_LO + r * 528 + col * 2) =
                            ((unsigned)__bfloat16_as_ushort(l1) << 16) | __bfloat16_as_ushort(l0);
                    }
                }
    }
    __syncthreads();

    // ===== GEMM2: 16 chunks (4 N-tiles x 4 K-chunks of 64); cosine fold ====
    float num[4] = {0, 0, 0, 0}, sq[4] = {0, 0, 0, 0};
    float acc2[2][8][4];
    for (int u = 0; u < 16; u++) {
        const int b = u & 1, c = u & 3, nt = u >> 2;
        if (u < 15) { stage_w2(u + 1, b ^ 1); CP_COMMIT(); CP_WAIT1(); }
        else        { CP_WAIT0(); }
        __syncthreads();
        if (c == 0) {
#pragma unroll
            for (int mi = 0; mi < 2; mi++)
#pragma unroll
                for (int ni = 0; ni < 8; ni++)
#pragma unroll
                    for (int e = 0; e < 4; e++) acc2[mi][ni][e] = 0.f;
        }
        uint32_t wbase = sbase + W2_BUF(b);
#pragma unroll
        for (int kk = 0; kk < 4; kk++) {
            const int kb = kk * 32;
            uint32_t ah[2][4], al[2][4];
#pragma unroll
            for (int mi = 0; mi < 2; mi++) {
                int ro = (m0 + mi * 16 + a_mrow) * 528 + c * 128 + kb + a_kh;
                ldsm4(ah[mi], sbase + HS_HI + ro);
                ldsm4(al[mi], sbase + HS_LO + ro);
            }
#pragma unroll
            for (int p = 0; p < 4; p++) {
                int ro = (wc * 64 + p * 16 + b_nrow) * 144 + kb + b_kh;
                uint32_t bh[4], bl[4];
                ldsm4(bh, wbase + W2H + ro);
                ldsm4(bl, wbase + W2L + ro);
#pragma unroll
                for (int mi = 0; mi < 2; mi++)
#pragma unroll
                    for (int e = 0; e < 2; e++) {
                        float* C = acc2[mi][p * 2 + e];
                        mma16816(C, ah[mi], bh + e * 2);
                        mma16816(C, ah[mi], bl + e * 2);
                        mma16816(C, al[mi], bh + e * 2);
                    }
            }
        }
        if (c == 3) {   // fold v = acc2 + b2 into cosine sums
#pragma unroll
            for (int mi = 0; mi < 2; mi++)
#pragma unroll
                for (int ni = 0; ni < 8; ni++) {
                    int col = nt * 128 + wc * 64 + ni * 8 + q4 * 2;
                    if (col < VD) {
                        float bb0 = b2s[col], bb1 = b2s[col + 1];
                        float cc0 = cts[col], cc1 = cts[col + 1];
                        float* C = acc2[mi][ni];
#pragma unroll
                        for (int rh = 0; rh < 2; rh++) {
                            int sl = mi * 2 + rh;
                            float v0 = C[rh * 2 + 0] + bb0;
                            float v1 = C[rh * 2 + 1] + bb1;
                            num[sl] = fmaf(v0, cc0, fmaf(v1, cc1, num[sl]));
                            sq[sl]  = fmaf(v0, v0, fmaf(v1, v1, sq[sl]));
                        }
                    }
                }
        }
        __syncthreads();
    }

    // ================= per-row cosine, block partial =======================
#pragma unroll
    for (int sl = 0; sl < 4; sl++)
#pragma unroll
        for (int o = 1; o < 4; o <<= 1) {
            num[sl] += __shfl_xor_sync(0xffffffffu, num[sl], o);
            sq[sl]  += __shfl_xor_sync(0xffffffffu, sq[sl], o);
        }
    if (q4 == 0) {
#pragma unroll
        for (int sl = 0; sl < 4; sl++) {
            int r = m0 + (sl >> 1) * 16 + (sl & 1) * 8 + g;
            red[wc * 128 + r] = num[sl];
            red[256 + wc * 128 + r] = sq[sl];
        }
    }
    __syncthreads();
    float rd = 0.f;
    if (wc == 0 && q4 == 0) {
        float cn = g_cnorm[t];
#pragma unroll
        for (int sl = 0; sl < 4; sl++) {
            int r = m0 + (sl >> 1) * 16 + (sl & 1) * 8 + g;
            float nu = red[r] + red[128 + r];
            float sv = red[256 + r] + red[384 + r];
            float vn = fmaxf(sqrtf(sv), 1e-8f);
            rd += 1.f - nu / (vn * cn);
        }
    }
#pragma unroll
    for (int o = 16; o > 0; o >>= 1) rd += __shfl_xor_sync(0xffffffffu, rd, o);
    if (wc == 0 && l == 0) red[512 + wr] = rd;
    __syncthreads();
    if (tid == 0)
        g_partial[t * NBLK + blockIdx.x] = red[512] + red[513] + red[514] + red[515];
}

__global__ void finalize_kernel(float* __restrict__ out, int out_size) {
    __shared__ float dist[T_TASKS];
    int t = threadIdx.x;
    if (t < T_TASKS) {
        float s = 0.f;
#pragma unroll
        for (int b = 0; b < NBLK; b++) s += g_partial[t * NBLK + b];
        float d = s * (1.0f / (float)B_ROWS);
        dist[t] = d;
        if (out_size >= T_TASKS) out[t] = d;
    }
    __syncthreads();
    if (t == 0) {
        int best = 0; float bv = dist[0];
        for (int i = 1; i < T_TASKS; i++)
            if (dist[i] < bv) { bv = dist[i]; best = i; }
        if (out_size >= T_TASKS + 1)      out[T_TASKS] = (float)best;
        else if (out_size >= 1 && out_size < T_TASKS) out[0] = (float)best;
    }
}

extern "C" void kernel_launch(void* const* d_in, const int* in_sizes, int n_in,
                              void* d_out, int out_size) {
    const float* t_feat = (const float*)d_in[0];
    const float* W1     = (const float*)d_in[1];
    const float* b1     = (const float*)d_in[2];
    const float* gamma  = (const float*)d_in[3];
    const float* beta   = (const float*)d_in[4];
    const float* W2     = (const float*)d_in[5];
    const float* b2     = (const float*)d_in[6];
    const float* cent   = (const float*)d_in[7];

    cudaFuncSetAttribute(router_mma, cudaFuncAttributeMaxDynamicSharedMemorySize, SMEM_BYTES);

    int cvt_blocks = (int)((CVT_TOTAL + 255) / 256);
    convert_kernel<<<cvt_blocks, 256>>>(t_feat, W1, W2);
    init_cnorm_kernel<<<T_TASKS, 128>>>(cent);
    dim3 grid(NBLK, T_TASKS);
    router_mma<<<grid, 256, SMEM_BYTES>>>(b1, gamma, beta, b2, cent);
    finalize_kernel<<<1, 64>>>((float*)d_out, out_size);
}

// round 11
// speedup vs baseline: 6.1911x; 1.4052x over previous
#include <cuda_runtime.h>
#include <cuda_bf16.h>
#include <math.h>
#include <stdint.h>

#define T_TASKS 64
#define B_ROWS  4096
#define TD      512
#define HD      256
#define VD      484
#define VDP     512
#define BM      128
#define NBLK    (B_ROWS / BM)   // 32

// ---- smem byte offsets ----
#define OFF_RED 0        // 544 floats
#define OFF_B1  2176
#define OFF_GM  3200
#define OFF_BT  4224
#define OFF_B2  5248
#define OFF_CT  7200     // ends 9136
// GEMM1 staging: KC=32, row stride 80 B, double buffered.
// per buffer: A_hi 10240, A_lo 10240, B_hi 256*80=20480  (NO B_lo: 2-pass split)
#define G1_BUF(b) (9216 + (b) * 40960)     // ends 91136
#define G1_AH 0
#define G1_AL 10240
#define G1_BH 20480
// H (post-GELU hi/lo bf16 [128][256], row stride 528 B) — reuses GEMM1 region
#define HS_HI 9216       // 128*528 = 67584
#define HS_LO 76800      // ends 144384
// GEMM2 W2 staging: KC=64, row stride 144 B, double buffered, hi only
#define W2_BUF(b) (144384 + (b) * 18432)   // ends 181248
#define SMEM_BYTES 181248

// ---- precomputed bf16 operands (tf: hi+lo; W1/W2: hi only) ----
#define TF_PAIRS  ((size_t)B_ROWS * TD / 2)
#define W1_PAIRS  ((size_t)T_TASKS * HD * TD / 2)
#define W2_PAIRS  ((size_t)T_TASKS * VDP * HD / 2)
#define CVT_TOTAL (TF_PAIRS + W1_PAIRS + W2_PAIRS)
__device__ uint4 g_tf_h[TF_PAIRS / 4];
__device__ uint4 g_tf_l[TF_PAIRS / 4];
__device__ uint4 g_w1_h[W1_PAIRS / 4];
__device__ uint4 g_w2_h[W2_PAIRS / 4];
__device__ float g_partial[T_TASKS * NBLK];
__device__ float g_cnorm[T_TASKS];

__device__ __forceinline__ uint32_t smem_u32(const void* p) {
    uint32_t a;
    asm("{ .reg .u64 t; cvta.to.shared.u64 t, %1; cvt.u32.u64 %0, t; }" : "=r"(a) : "l"(p));
    return a;
}
__device__ __forceinline__ void ldsm4(uint32_t* r, uint32_t addr) {
    asm volatile("ldmatrix.sync.aligned.m8n8.x4.shared.b16 {%0,%1,%2,%3}, [%4];"
        : "=r"(r[0]), "=r"(r[1]), "=r"(r[2]), "=r"(r[3]) : "r"(addr));
}
__device__ __forceinline__ void mma16816(float* d, const uint32_t* a, const uint32_t* b) {
    asm volatile("mma.sync.aligned.m16n8k16.row.col.f32.bf16.bf16.f32 "
        "{%0,%1,%2,%3}, {%4,%5,%6,%7}, {%8,%9}, {%0,%1,%2,%3};"
        : "+f"(d[0]), "+f"(d[1]), "+f"(d[2]), "+f"(d[3])
        : "r"(a[0]), "r"(a[1]), "r"(a[2]), "r"(a[3]), "r"(b[0]), "r"(b[1]));
}
__device__ __forceinline__ void cpa16(uint32_t dst, const void* src) {
    asm volatile("cp.async.cg.shared.global [%0], [%1], 16;" :: "r"(dst), "l"(src));
}
#define CP_COMMIT() asm volatile("cp.async.commit_group;" ::: "memory")
#define CP_WAIT0()  asm volatile("cp.async.wait_group 0;" ::: "memory")
#define CP_WAIT1()  asm volatile("cp.async.wait_group 1;" ::: "memory")

// ---------------------------------------------------------------------------
// convert: tf -> bf16 hi/lo; W1, W2 -> bf16 hi only (W2 padded to VDP rows)
// ---------------------------------------------------------------------------
__global__ void convert_kernel(const float* __restrict__ tf,
                               const float* __restrict__ W1,
                               const float* __restrict__ W2) {
    size_t p = (size_t)blockIdx.x * blockDim.x + threadIdx.x;
    if (p >= CVT_TOTAL) return;
    if (p < TF_PAIRS) {
        float x0 = tf[2 * p], x1 = tf[2 * p + 1];
        __nv_bfloat16 h0 = __float2bfloat16(x0), h1 = __float2bfloat16(x1);
        __nv_bfloat16 l0 = __float2bfloat16(x0 - __bfloat162float(h0));
        __nv_bfloat16 l1 = __float2bfloat16(x1 - __bfloat162float(h1));
        ((unsigned*)g_tf_h)[p] = ((unsigned)__bfloat16_as_ushort(h1) << 16) | __bfloat16_as_ushort(h0);
        ((unsigned*)g_tf_l)[p] = ((unsigned)__bfloat16_as_ushort(l1) << 16) | __bfloat16_as_ushort(l0);
    } else if (p < TF_PAIRS + W1_PAIRS) {
        size_t idx = p - TF_PAIRS;
        float x0 = W1[2 * idx], x1 = W1[2 * idx + 1];
        __nv_bfloat16 h0 = __float2bfloat16(x0), h1 = __float2bfloat16(x1);
        ((unsigned*)g_w1_h)[idx] = ((unsigned)__bfloat16_as_ushort(h1) << 16) | __bfloat16_as_ushort(h0);
    } else {
        size_t idx = p - TF_PAIRS - W1_PAIRS;
        size_t per_task = (size_t)VDP * HD / 2;
        size_t t = idx / per_task, r = idx % per_task;
        size_t n = r / (HD / 2), k2 = r % (HD / 2);
        float x0 = 0.f, x1 = 0.f;
        if (n < VD) {
            const float* s = W2 + t * (size_t)VD * HD + n * HD + 2 * k2;
            x0 = s[0]; x1 = s[1];
        }
        __nv_bfloat16 h0 = __float2bfloat16(x0), h1 = __float2bfloat16(x1);
        ((unsigned*)g_w2_h)[idx] = ((unsigned)__bfloat16_as_ushort(h1) << 16) | __bfloat16_as_ushort(h0);
    }
}

__global__ void init_cnorm_kernel(const float* __restrict__ cent) {
    int t = blockIdx.x;
    float s = 0.f;
    for (int n = threadIdx.x; n < VD; n += 128) {
        float c = cent[t * VD + n];
        s = fmaf(c, c, s);
    }
#pragma unroll
    for (int o = 16; o > 0; o >>= 1) s += __shfl_xor_sync(0xffffffffu, s, o);
    __shared__ float ws[4];
    if ((threadIdx.x & 31) == 0) ws[threadIdx.x >> 5] = s;
    __syncthreads();
    if (threadIdx.x == 0) g_cnorm[t] = fmaxf(sqrtf(ws[0] + ws[1] + ws[2] + ws[3]), 1e-8f);
}

// ---------------------------------------------------------------------------
// fused HMMA router, cp.async double-buffered, 2-pass split (weights bf16-hi)
// ---------------------------------------------------------------------------
__global__ __launch_bounds__(256, 1)
void router_mma(const float* __restrict__ b1v, const float* __restrict__ gamma,
                const float* __restrict__ beta, const float* __restrict__ b2v,
                const float* __restrict__ cent) {
    extern __shared__ char smem[];
    const uint32_t sbase = smem_u32(smem);
    const int tid = threadIdx.x;
    const int w = tid >> 5, l = tid & 31;
    const int wr = w & 3, wc = w >> 2;
    const int m0 = wr * 32;
    const int g  = l >> 2, q4 = l & 3;
    const int t = blockIdx.y;
    const int brow0 = blockIdx.x * BM;

    float* red = (float*)(smem + OFF_RED);
    float* b1s = (float*)(smem + OFF_B1);
    float* gms = (float*)(smem + OFF_GM);
    float* bts = (float*)(smem + OFF_BT);
    float* b2s = (float*)(smem + OFF_B2);
    float* cts = (float*)(smem + OFF_CT);

    if (tid < HD) {
        b1s[tid] = b1v[t * HD + tid];
        gms[tid] = gamma[t * HD + tid];
        bts[tid] = beta[t * HD + tid];
    }
    for (int i = tid; i < VD; i += 256) {
        b2s[i] = b2v[(size_t)t * VD + i];
        cts[i] = cent[(size_t)t * VD + i];
    }

    const int a_mrow = ((l >> 3) & 1) * 8 + (l & 7);
    const int a_kh   = (l >> 4) * 16;
    const int b_nrow = (l >> 4) * 8 + (l & 7);
    const int b_kh   = ((l >> 3) & 1) * 16;

    // ---- staging (cp.async) ----
    auto stage_g1 = [&](int c, int b) {
        uint32_t base = sbase + G1_BUF(b);
#pragma unroll
        for (int q = tid; q < 512; q += 256) {            // A: 128 rows x 4 uint4 (hi+lo)
            int r = q >> 2, i = q & 3;
            size_t gi = (size_t)(brow0 + r) * 64 + (size_t)c * 4 + i;
            int off = r * 80 + i * 16;
            cpa16(base + G1_AH + off, &g_tf_h[gi]);
            cpa16(base + G1_AL + off, &g_tf_l[gi]);
        }
#pragma unroll
        for (int q = tid; q < 1024; q += 256) {           // B=W1 hi: 256 rows x 4 uint4
            int r = q >> 2, i = q & 3;
            size_t gi = (size_t)t * 16384 + (size_t)r * 64 + (size_t)c * 4 + i;
            cpa16(base + G1_BH + r * 80 + i * 16, &g_w1_h[gi]);
        }
    };
    auto stage_w2 = [&](int u, int b) {                   // u = nt*4 + c (KC=64), hi only
        int nt = u >> 2, c = u & 3;
        uint32_t base = sbase + W2_BUF(b);
#pragma unroll
        for (int q = tid; q < 1024; q += 256) {           // 128 rows x 8 uint4
            int r = q >> 3, i = q & 7;
            size_t gi = (size_t)t * 16384 + (size_t)(nt * 128 + r) * 32 + (size_t)c * 8 + i;
            cpa16(base + r * 144 + i * 16, &g_w2_h[gi]);
        }
    };

    // ===================== GEMM1 (16 chunks of KC=32) ======================
    float acc[2][2][8][4];
#pragma unroll
    for (int h = 0; h < 2; h++)
#pragma unroll
        for (int mi = 0; mi < 2; mi++)
#pragma unroll
            for (int ni = 0; ni < 8; ni++)
#pragma unroll
                for (int e = 0; e < 4; e++) acc[h][mi][ni][e] = 0.f;

    stage_g1(0, 0);
    CP_COMMIT();
    for (int c = 0; c < 16; c++) {
        const int b = c & 1;
        if (c < 15) { stage_g1(c + 1, b ^ 1); CP_COMMIT(); CP_WAIT1(); }
        else        { CP_WAIT0(); }
        __syncthreads();
        uint32_t abase = sbase + G1_BUF(b);
#pragma unroll
        for (int kk = 0; kk < 2; kk++) {
            const int kb = kk * 32;
            uint32_t ah[2][4], al[2][4];
#pragma unroll
            for (int mi = 0; mi < 2; mi++) {
                int ro = (m0 + mi * 16 + a_mrow) * 80 + kb + a_kh;
                ldsm4(ah[mi], abase + G1_AH + ro);
                ldsm4(al[mi], abase + G1_AL + ro);
            }
#pragma unroll
            for (int h = 0; h < 2; h++) {
#pragma unroll
                for (int p = 0; p < 4; p++) {
                    int ro = (h * 128 + wc * 64 + p * 16 + b_nrow) * 80 + kb + b_kh;
                    uint32_t bh[4];
                    ldsm4(bh, abase + G1_BH + ro);
#pragma unroll
                    for (int mi = 0; mi < 2; mi++)
#pragma unroll
                        for (int e = 0; e < 2; e++) {
                            float* C = acc[h][mi][p * 2 + e];
                            mma16816(C, ah[mi], bh + e * 2);
                            mma16816(C, al[mi], bh + e * 2);
                        }
                }
            }
        }
        __syncthreads();
    }

    // prefetch first W2 chunk under the epilogue
    stage_w2(0, 0);
    CP_COMMIT();

    // ======= epilogue 1: bias + LayerNorm + GELU -> H hi/lo smem ===========
    {
        float s[4] = {0, 0, 0, 0}, s2[4] = {0, 0, 0, 0};
#pragma unroll
        for (int h = 0; h < 2; h++)
#pragma unroll
            for (int mi = 0; mi < 2; mi++)
#pragma unroll
                for (int ni = 0; ni < 8; ni++) {
                    int col = h * 128 + wc * 64 + ni * 8 + q4 * 2;
                    float bb0 = b1s[col], bb1 = b1s[col + 1];
                    float* C = acc[h][mi][ni];
                    C[0] += bb0; C[1] += bb1; C[2] += bb0; C[3] += bb1;
                    s[mi * 2 + 0] += C[0] + C[1];
                    s2[mi * 2 + 0] = fmaf(C[0], C[0], fmaf(C[1], C[1], s2[mi * 2 + 0]));
                    s[mi * 2 + 1] += C[2] + C[3];
                    s2[mi * 2 + 1] = fmaf(C[2], C[2], fmaf(C[3], C[3], s2[mi * 2 + 1]));
                }
#pragma unroll
        for (int sl = 0; sl < 4; sl++)
#pragma unroll
            for (int o = 1; o < 4; o <<= 1) {
                s[sl]  += __shfl_xor_sync(0xffffffffu, s[sl], o);
                s2[sl] += __shfl_xor_sync(0xffffffffu, s2[sl], o);
            }
        if (q4 == 0) {
#pragma unroll
            for (int sl = 0; sl < 4; sl++) {
                int r = m0 + (sl >> 1) * 16 + (sl & 1) * 8 + g;
                red[wc * 128 + r] = s[sl];
                red[256 + wc * 128 + r] = s2[sl];
            }
        }
        __syncthreads();
        float mu[4], rs[4];
#pragma unroll
        for (int sl = 0; sl < 4; sl++) {
            int r = m0 + (sl >> 1) * 16 + (sl & 1) * 8 + g;
            float ts  = red[r] + red[128 + r];
            float ts2 = red[256 + r] + red[384 + r];
            mu[sl] = ts * (1.f / HD);
            rs[sl] = rsqrtf(ts2 * (1.f / HD) - mu[sl] * mu[sl] + 1e-5f);
        }
        __syncthreads();
#pragma unroll
        for (int h = 0; h < 2; h++)
#pragma unroll
            for (int mi = 0; mi < 2; mi++)
#pragma unroll
                for (int ni = 0; ni < 8; ni++) {
                    int col = h * 128 + wc * 64 + ni * 8 + q4 * 2;
                    float gm0 = gms[col], gm1 = gms[col + 1];
                    float bt0 = bts[col], bt1 = bts[col + 1];
                    float* C = acc[h][mi][ni];
#pragma unroll
                    for (int rh = 0; rh < 2; rh++) {
                        int sl = mi * 2 + rh;
                        int r = m0 + mi * 16 + rh * 8 + g;
                        float y0 = (C[rh * 2 + 0] - mu[sl]) * rs[sl] * gm0 + bt0;
                        float y1 = (C[rh * 2 + 1] - mu[sl]) * rs[sl] * gm1 + bt1;
                        float g0 = 0.5f * y0 * (1.f + erff(y0 * 0.70710678118654752f));
                        float g1 = 0.5f * y1 * (1.f + erff(y1 * 0.70710678118654752f));
                        __nv_bfloat16 h0 = __float2bfloat16(g0), h1 = __float2bfloat16(g1);
                        __nv_bfloat16 l0 = __float2bfloat16(g0 - __bfloat162float(h0));
                        __nv_bfloat16 l1 = __float2bfloat16(g1 - __bfloat162float(h1));
                        *(unsigned*)(smem + HS_HI + r * 528 + col * 2) =
                            ((unsigned)__bfloat16_as_ushort(h1) << 16) | __bfloat16_as_ushort(h0);
                        *(unsigned*)(smem + HS_LO + r * 528 + col * 2) =
                            ((unsigned)__bfloat16_as_ushort(l1) << 16) | __bfloat16_as_ushort(l0);
                    }
                }
    }
    __syncthreads();

    // ===== GEMM2: 16 chunks (4 N-tiles x 4 K-chunks of 64); cosine fold ====
    float num[4] = {0, 0, 0, 0}, sq[4] = {0, 0, 0, 0};
    float acc2[2][8][4];
    for (int u = 0; u < 16; u++) {
        const int b = u & 1, c = u & 3, nt = u >> 2;
        if (u < 15) { stage_w2(u + 1, b ^ 1); CP_COMMIT(); CP_WAIT1(); }
        else        { CP_WAIT0(); }
        __syncthreads();
        if (c == 0) {
#pragma unroll
            for (int mi = 0; mi < 2; mi++)
#pragma unroll
                for (int ni = 0; ni < 8; ni++)
#pragma unroll
                    for (int e = 0; e < 4; e++) acc2[mi][ni][e] = 0.f;
        }
        uint32_t wbase = sbase + W2_BUF(b);
#pragma unroll
        for (int kk = 0; kk < 4; kk++) {
            const int kb = kk * 32;
            uint32_t ah[2][4], al[2][4];
#pragma unroll
            for (int mi = 0; mi < 2; mi++) {
                int ro = (m0 + mi * 16 + a_mrow) * 528 + c * 128 + kb + a_kh;
                ldsm4(ah[mi], sbase + HS_HI + ro);
                ldsm4(al[mi], sbase + HS_LO + ro);
            }
#pragma unroll
            for (int p = 0; p < 4; p++) {
                int ro = (wc * 64 + p * 16 + b_nrow) * 144 + kb + b_kh;
                uint32_t bh[4];
                ldsm4(bh, wbase + ro);
#pragma unroll
                for (int mi = 0; mi < 2; mi++)
#pragma unroll
                    for (int e = 0; e < 2; e++) {
                        float* C = acc2[mi][p * 2 + e];
                        mma16816(C, ah[mi], bh + e * 2);
                        mma16816(C, al[mi], bh + e * 2);
                    }
            }
        }
        if (c == 3) {   // fold v = acc2 + b2 into cosine sums
#pragma unroll
            for (int mi = 0; mi < 2; mi++)
#pragma unroll
                for (int ni = 0; ni < 8; ni++) {
                    int col = nt * 128 + wc * 64 + ni * 8 + q4 * 2;
                    if (col < VD) {
                        float bb0 = b2s[col], bb1 = b2s[col + 1];
                        float cc0 = cts[col], cc1 = cts[col + 1];
                        float* C = acc2[mi][ni];
#pragma unroll
                        for (int rh = 0; rh < 2; rh++) {
                            int sl = mi * 2 + rh;
                            float v0 = C[rh * 2 + 0] + bb0;
                            float v1 = C[rh * 2 + 1] + bb1;
                            num[sl] = fmaf(v0, cc0, fmaf(v1, cc1, num[sl]));
                            sq[sl]  = fmaf(v0, v0, fmaf(v1, v1, sq[sl]));
                        }
                    }
                }
        }
        __syncthreads();
    }

    // ================= per-row cosine, block partial =======================
#pragma unroll
    for (int sl = 0; sl < 4; sl++)
#pragma unroll
        for (int o = 1; o < 4; o <<= 1) {
            num[sl] += __shfl_xor_sync(0xffffffffu, num[sl], o);
            sq[sl]  += __shfl_xor_sync(0xffffffffu, sq[sl], o);
        }
    if (q4 == 0) {
#pragma unroll
        for (int sl = 0; sl < 4; sl++) {
            int r = m0 + (sl >> 1) * 16 + (sl & 1) * 8 + g;
            red[wc * 128 + r] = num[sl];
            red[256 + wc * 128 + r] = sq[sl];
        }
    }
    __syncthreads();
    float rd = 0.f;
    if (wc == 0 && q4 == 0) {
        float cn = g_cnorm[t];
#pragma unroll
        for (int sl = 0; sl < 4; sl++) {
            int r = m0 + (sl >> 1) * 16 + (sl & 1) * 8 + g;
            float nu = red[r] + red[128 + r];
            float sv = red[256 + r] + red[384 + r];
            float vn = fmaxf(sqrtf(sv), 1e-8f);
            rd += 1.f - nu / (vn * cn);
        }
    }
#pragma unroll
    for (int o = 16; o > 0; o >>= 1) rd += __shfl_xor_sync(0xffffffffu, rd, o);
    if (wc == 0 && l == 0) red[512 + wr] = rd;
    __syncthreads();
    if (tid == 0)
        g_partial[t * NBLK + blockIdx.x] = red[512] + red[513] + red[514] + red[515];
}

__global__ void finalize_kernel(float* __restrict__ out, int out_size) {
    __shared__ float dist[T_TASKS];
    int t = threadIdx.x;
    if (t < T_TASKS) {
        float s = 0.f;
#pragma unroll
        for (int b = 0; b < NBLK; b++) s += g_partial[t * NBLK + b];
        float d = s * (1.0f / (float)B_ROWS);
        dist[t] = d;
        if (out_size >= T_TASKS) out[t] = d;
    }
    __syncthreads();
    if (t == 0) {
        int best = 0; float bv = dist[0];
        for (int i = 1; i < T_TASKS; i++)
            if (dist[i] < bv) { bv = dist[i]; best = i; }
        if (out_size >= T_TASKS + 1)      out[T_TASKS] = (float)best;
        else if (out_size >= 1 && out_size < T_TASKS) out[0] = (float)best;
    }
}

extern "C" void kernel_launch(void* const* d_in, const int* in_sizes, int n_in,
                              void* d_out, int out_size) {
    const float* t_feat = (const float*)d_in[0];
    const float* W1     = (const float*)d_in[1];
    const float* b1     = (const float*)d_in[2];
    const float* gamma  = (const float*)d_in[3];
    const float* beta   = (const float*)d_in[4];
    const float* W2     = (const float*)d_in[5];
    const float* b2     = (const float*)d_in[6];
    const float* cent   = (const float*)d_in[7];

    cudaFuncSetAttribute(router_mma, cudaFuncAttributeMaxDynamicSharedMemorySize, SMEM_BYTES);

    int cvt_blocks = (int)((CVT_TOTAL + 255) / 256);
    convert_kernel<<<cvt_blocks, 256>>>(t_feat, W1, W2);
    init_cnorm_kernel<<<T_TASKS, 128>>>(cent);
    dim3 grid(NBLK, T_TASKS);
    router_mma<<<grid, 256, SMEM_BYTES>>>(b1, gamma, beta, b2, cent);
    finalize_kernel<<<1, 64>>>((float*)d_out, out_size);
}

// round 12
// speedup vs baseline: 9.5439x; 1.5416x over previous
#include <cuda_runtime.h>
#include <cuda_bf16.h>
#include <math.h>
#include <stdint.h>

#define T_TASKS 64
#define B_ROWS  4096
#define TD      512
#define HD      256
#define VD      484
#define VDP     512
#define BM      128
#define NBLK    (B_ROWS / BM)   // 32

// ---- smem byte offsets ----
#define OFF_RED 0        // 544 floats
#define OFF_B1  2176
#define OFF_GM  3200
#define OFF_BT  4224
#define OFF_B2  5248
#define OFF_CT  7200     // ends 9136
// GEMM1 staging: KC=64, row stride 144 B, double buffered, bf16 only.
// per buffer: A 128*144=18432, B 256*144=36864  -> 55296
#define G1_BUF(b) (9216 + (b) * 55296)     // ends 119808
#define G1_A  0
#define G1_B  18432
// H (post-GELU bf16 [128][256], row stride 528 B) — reuses GEMM1 region
#define HS    9216       // 128*528 = 67584, ends 76800
// GEMM2 W2 staging: KC=64, row stride 144 B, double buffered
#define W2_BUF(b) (119808 + (b) * 18432)   // ends 156672
#define SMEM_BYTES 156672

// ---- precomputed bf16 operands (all hi only) ----
#define TF_PAIRS  ((size_t)B_ROWS * TD / 2)
#define W1_PAIRS  ((size_t)T_TASKS * HD * TD / 2)
#define W2_PAIRS  ((size_t)T_TASKS * VDP * HD / 2)
#define CVT_TOTAL (TF_PAIRS + W1_PAIRS + W2_PAIRS)
__device__ uint4 g_tf_h[TF_PAIRS / 4];
__device__ uint4 g_w1_h[W1_PAIRS / 4];
__device__ uint4 g_w2_h[W2_PAIRS / 4];
__device__ float g_partial[T_TASKS * NBLK];
__device__ float g_cnorm[T_TASKS];

__device__ __forceinline__ uint32_t smem_u32(const void* p) {
    uint32_t a;
    asm("{ .reg .u64 t; cvta.to.shared.u64 t, %1; cvt.u32.u64 %0, t; }" : "=r"(a) : "l"(p));
    return a;
}
__device__ __forceinline__ void ldsm4(uint32_t* r, uint32_t addr) {
    asm volatile("ldmatrix.sync.aligned.m8n8.x4.shared.b16 {%0,%1,%2,%3}, [%4];"
        : "=r"(r[0]), "=r"(r[1]), "=r"(r[2]), "=r"(r[3]) : "r"(addr));
}
__device__ __forceinline__ void mma16816(float* d, const uint32_t* a, const uint32_t* b) {
    asm volatile("mma.sync.aligned.m16n8k16.row.col.f32.bf16.bf16.f32 "
        "{%0,%1,%2,%3}, {%4,%5,%6,%7}, {%8,%9}, {%0,%1,%2,%3};"
        : "+f"(d[0]), "+f"(d[1]), "+f"(d[2]), "+f"(d[3])
        : "r"(a[0]), "r"(a[1]), "r"(a[2]), "r"(a[3]), "r"(b[0]), "r"(b[1]));
}
__device__ __forceinline__ void cpa16(uint32_t dst, const void* src) {
    asm volatile("cp.async.cg.shared.global [%0], [%1], 16;" :: "r"(dst), "l"(src));
}
#define CP_COMMIT() asm volatile("cp.async.commit_group;" ::: "memory")
#define CP_WAIT0()  asm volatile("cp.async.wait_group 0;" ::: "memory")
#define CP_WAIT1()  asm volatile("cp.async.wait_group 1;" ::: "memory")

// ---------------------------------------------------------------------------
// convert: tf, W1, W2 -> bf16 (W2 padded to VDP rows)
// ---------------------------------------------------------------------------
__global__ void convert_kernel(const float* __restrict__ tf,
                               const float* __restrict__ W1,
                               const float* __restrict__ W2) {
    size_t p = (size_t)blockIdx.x * blockDim.x + threadIdx.x;
    if (p >= CVT_TOTAL) return;
    float x0, x1; unsigned* dst; size_t idx;
    if (p < TF_PAIRS) {
        idx = p; x0 = tf[2 * p]; x1 = tf[2 * p + 1];
        dst = (unsigned*)g_tf_h;
    } else if (p < TF_PAIRS + W1_PAIRS) {
        idx = p - TF_PAIRS; x0 = W1[2 * idx]; x1 = W1[2 * idx + 1];
        dst = (unsigned*)g_w1_h;
    } else {
        idx = p - TF_PAIRS - W1_PAIRS;
        size_t per_task = (size_t)VDP * HD / 2;
        size_t t = idx / per_task, r = idx % per_task;
        size_t n = r / (HD / 2), k2 = r % (HD / 2);
        x0 = 0.f; x1 = 0.f;
        if (n < VD) {
            const float* s = W2 + t * (size_t)VD * HD + n * HD + 2 * k2;
            x0 = s[0]; x1 = s[1];
        }
        dst = (unsigned*)g_w2_h;
    }
    __nv_bfloat16 h0 = __float2bfloat16(x0), h1 = __float2bfloat16(x1);
    dst[idx] = ((unsigned)__bfloat16_as_ushort(h1) << 16) | __bfloat16_as_ushort(h0);
}

__global__ void init_cnorm_kernel(const float* __restrict__ cent) {
    int t = blockIdx.x;
    float s = 0.f;
    for (int n = threadIdx.x; n < VD; n += 128) {
        float c = cent[t * VD + n];
        s = fmaf(c, c, s);
    }
#pragma unroll
    for (int o = 16; o > 0; o >>= 1) s += __shfl_xor_sync(0xffffffffu, s, o);
    __shared__ float ws[4];
    if ((threadIdx.x & 31) == 0) ws[threadIdx.x >> 5] = s;
    __syncthreads();
    if (threadIdx.x == 0) g_cnorm[t] = fmaxf(sqrtf(ws[0] + ws[1] + ws[2] + ws[3]), 1e-8f);
}

// ---------------------------------------------------------------------------
// fused HMMA router, cp.async double-buffered, pure bf16 operands
// ---------------------------------------------------------------------------
__global__ __launch_bounds__(256, 1)
void router_mma(const float* __restrict__ b1v, const float* __restrict__ gamma,
                const float* __restrict__ beta, const float* __restrict__ b2v,
                const float* __restrict__ cent) {
    extern __shared__ char smem[];
    const uint32_t sbase = smem_u32(smem);
    const int tid = threadIdx.x;
    const int w = tid >> 5, l = tid & 31;
    const int wr = w & 3, wc = w >> 2;
    const int m0 = wr * 32;
    const int g  = l >> 2, q4 = l & 3;
    const int t = blockIdx.y;
    const int brow0 = blockIdx.x * BM;

    float* red = (float*)(smem + OFF_RED);
    float* b1s = (float*)(smem + OFF_B1);
    float* gms = (float*)(smem + OFF_GM);
    float* bts = (float*)(smem + OFF_BT);
    float* b2s = (float*)(smem + OFF_B2);
    float* cts = (float*)(smem + OFF_CT);

    if (tid < HD) {
        b1s[tid] = b1v[t * HD + tid];
        gms[tid] = gamma[t * HD + tid];
        bts[tid] = beta[t * HD + tid];
    }
    for (int i = tid; i < VD; i += 256) {
        b2s[i] = b2v[(size_t)t * VD + i];
        cts[i] = cent[(size_t)t * VD + i];
    }

    const int a_mrow = ((l >> 3) & 1) * 8 + (l & 7);
    const int a_kh   = (l >> 4) * 16;
    const int b_nrow = (l >> 4) * 8 + (l & 7);
    const int b_kh   = ((l >> 3) & 1) * 16;

    // ---- staging (cp.async), KC=64 everywhere ----
    auto stage_g1 = [&](int c, int b) {
        uint32_t base = sbase + G1_BUF(b);
#pragma unroll
        for (int q = tid; q < 1024; q += 256) {           // A: 128 rows x 8 uint4
            int r = q >> 3, i = q & 7;
            size_t gi = (size_t)(brow0 + r) * 64 + (size_t)c * 8 + i;
            cpa16(base + G1_A + r * 144 + i * 16, &g_tf_h[gi]);
        }
#pragma unroll
        for (int q = tid; q < 2048; q += 256) {           // B=W1: 256 rows x 8 uint4
            int r = q >> 3, i = q & 7;
            size_t gi = (size_t)t * 16384 + (size_t)r * 64 + (size_t)c * 8 + i;
            cpa16(base + G1_B + r * 144 + i * 16, &g_w1_h[gi]);
        }
    };
    auto stage_w2 = [&](int u, int b) {                   // u = nt*4 + c
        int nt = u >> 2, c = u & 3;
        uint32_t base = sbase + W2_BUF(b);
#pragma unroll
        for (int q = tid; q < 1024; q += 256) {           // 128 rows x 8 uint4
            int r = q >> 3, i = q & 7;
            size_t gi = (size_t)t * 16384 + (size_t)(nt * 128 + r) * 32 + (size_t)c * 8 + i;
            cpa16(base + r * 144 + i * 16, &g_w2_h[gi]);
        }
    };

    // ===================== GEMM1 (8 chunks of KC=64) =======================
    float acc[2][2][8][4];
#pragma unroll
    for (int h = 0; h < 2; h++)
#pragma unroll
        for (int mi = 0; mi < 2; mi++)
#pragma unroll
            for (int ni = 0; ni < 8; ni++)
#pragma unroll
                for (int e = 0; e < 4; e++) acc[h][mi][ni][e] = 0.f;

    stage_g1(0, 0);
    CP_COMMIT();
    for (int c = 0; c < 8; c++) {
        const int b = c & 1;
        if (c < 7) { stage_g1(c + 1, b ^ 1); CP_COMMIT(); CP_WAIT1(); }
        else       { CP_WAIT0(); }
        __syncthreads();
        uint32_t abase = sbase + G1_BUF(b);
#pragma unroll
        for (int kk = 0; kk < 4; kk++) {
            const int kb = kk * 32;
            uint32_t ah[2][4];
#pragma unroll
            for (int mi = 0; mi < 2; mi++) {
                int ro = (m0 + mi * 16 + a_mrow) * 144 + kb + a_kh;
                ldsm4(ah[mi], abase + G1_A + ro);
            }
#pragma unroll
            for (int h = 0; h < 2; h++) {
#pragma unroll
                for (int p = 0; p < 4; p++) {
                    int ro = (h * 128 + wc * 64 + p * 16 + b_nrow) * 144 + kb + b_kh;
                    uint32_t bh[4];
                    ldsm4(bh, abase + G1_B + ro);
#pragma unroll
                    for (int mi = 0; mi < 2; mi++)
#pragma unroll
                        for (int e = 0; e < 2; e++)
                            mma16816(acc[h][mi][p * 2 + e], ah[mi], bh + e * 2);
                }
            }
        }
        __syncthreads();
    }

    // prefetch first W2 chunk under the epilogue
    stage_w2(0, 0);
    CP_COMMIT();

    // ======= epilogue 1: bias + LayerNorm + GELU -> H bf16 smem ============
    {
        float s[4] = {0, 0, 0, 0}, s2[4] = {0, 0, 0, 0};
#pragma unroll
        for (int h = 0; h < 2; h++)
#pragma unroll
            for (int mi = 0; mi < 2; mi++)
#pragma unroll
                for (int ni = 0; ni < 8; ni++) {
                    int col = h * 128 + wc * 64 + ni * 8 + q4 * 2;
                    float bb0 = b1s[col], bb1 = b1s[col + 1];
                    float* C = acc[h][mi][ni];
                    C[0] += bb0; C[1] += bb1; C[2] += bb0; C[3] += bb1;
                    s[mi * 2 + 0] += C[0] + C[1];
                    s2[mi * 2 + 0] = fmaf(C[0], C[0], fmaf(C[1], C[1], s2[mi * 2 + 0]));
                    s[mi * 2 + 1] += C[2] + C[3];
                    s2[mi * 2 + 1] = fmaf(C[2], C[2], fmaf(C[3], C[3], s2[mi * 2 + 1]));
                }
#pragma unroll
        for (int sl = 0; sl < 4; sl++)
#pragma unroll
            for (int o = 1; o < 4; o <<= 1) {
                s[sl]  += __shfl_xor_sync(0xffffffffu, s[sl], o);
                s2[sl] += __shfl_xor_sync(0xffffffffu, s2[sl], o);
            }
        if (q4 == 0) {
#pragma unroll
            for (int sl = 0; sl < 4; sl++) {
                int r = m0 + (sl >> 1) * 16 + (sl & 1) * 8 + g;
                red[wc * 128 + r] = s[sl];
                red[256 + wc * 128 + r] = s2[sl];
            }
        }
        __syncthreads();
        float mu[4], rs[4];
#pragma unroll
        for (int sl = 0; sl < 4; sl++) {
            int r = m0 + (sl >> 1) * 16 + (sl & 1) * 8 + g;
            float ts  = red[r] + red[128 + r];
            float ts2 = red[256 + r] + red[384 + r];
            mu[sl] = ts * (1.f / HD);
            rs[sl] = rsqrtf(ts2 * (1.f / HD) - mu[sl] * mu[sl] + 1e-5f);
        }
        __syncthreads();
#pragma unroll
        for (int h = 0; h < 2; h++)
#pragma unroll
            for (int mi = 0; mi < 2; mi++)
#pragma unroll
                for (int ni = 0; ni < 8; ni++) {
                    int col = h * 128 + wc * 64 + ni * 8 + q4 * 2;
                    float gm0 = gms[col], gm1 = gms[col + 1];
                    float bt0 = bts[col], bt1 = bts[col + 1];
                    float* C = acc[h][mi][ni];
#pragma unroll
                    for (int rh = 0; rh < 2; rh++) {
                        int sl = mi * 2 + rh;
                        int r = m0 + mi * 16 + rh * 8 + g;
                        float y0 = (C[rh * 2 + 0] - mu[sl]) * rs[sl] * gm0 + bt0;
                        float y1 = (C[rh * 2 + 1] - mu[sl]) * rs[sl] * gm1 + bt1;
                        float g0 = 0.5f * y0 * (1.f + erff(y0 * 0.70710678118654752f));
                        float g1 = 0.5f * y1 * (1.f + erff(y1 * 0.70710678118654752f));
                        __nv_bfloat16 h0 = __float2bfloat16(g0), h1 = __float2bfloat16(g1);
                        *(unsigned*)(smem + HS + r * 528 + col * 2) =
                            ((unsigned)__bfloat16_as_ushort(h1) << 16) | __bfloat16_as_ushort(h0);
                    }
                }
    }
    __syncthreads();

    // ===== GEMM2: 16 chunks (4 N-tiles x 4 K-chunks of 64); cosine fold ====
    float num[4] = {0, 0, 0, 0}, sq[4] = {0, 0, 0, 0};
    float acc2[2][8][4];
    for (int u = 0; u < 16; u++) {
        const int b = u & 1, c = u & 3, nt = u >> 2;
        if (u < 15) { stage_w2(u + 1, b ^ 1); CP_COMMIT(); CP_WAIT1(); }
        else        { CP_WAIT0(); }
        __syncthreads();
        if (c == 0) {
#pragma unroll
            for (int mi = 0; mi < 2; mi++)
#pragma unroll
                for (int ni = 0; ni < 8; ni++)
#pragma unroll
                    for (int e = 0; e < 4; e++) acc2[mi][ni][e] = 0.f;
        }
        uint32_t wbase = sbase + W2_BUF(b);
#pragma unroll
        for (int kk = 0; kk < 4; kk++) {
            const int kb = kk * 32;
            uint32_t ah[2][4];
#pragma unroll
            for (int mi = 0; mi < 2; mi++) {
                int ro = (m0 + mi * 16 + a_mrow) * 528 + c * 128 + kb + a_kh;
                ldsm4(ah[mi], sbase + HS + ro);
            }
#pragma unroll
            for (int p = 0; p < 4; p++) {
                int ro = (wc * 64 + p * 16 + b_nrow) * 144 + kb + b_kh;
                uint32_t bh[4];
                ldsm4(bh, wbase + ro);
#pragma unroll
                for (int mi = 0; mi < 2; mi++)
#pragma unroll
                    for (int e = 0; e < 2; e++)
                        mma16816(acc2[mi][p * 2 + e], ah[mi], bh + e * 2);
            }
        }
        if (c == 3) {   // fold v = acc2 + b2 into cosine sums
#pragma unroll
            for (int mi = 0; mi < 2; mi++)
#pragma unroll
                for (int ni = 0; ni < 8; ni++) {
                    int col = nt * 128 + wc * 64 + ni * 8 + q4 * 2;
                    if (col < VD) {
                        float bb0 = b2s[col], bb1 = b2s[col + 1];
                        float cc0 = cts[col], cc1 = cts[col + 1];
                        float* C = acc2[mi][ni];
#pragma unroll
                        for (int rh = 0; rh < 2; rh++) {
                            int sl = mi * 2 + rh;
                            float v0 = C[rh * 2 + 0] + bb0;
                            float v1 = C[rh * 2 + 1] + bb1;
                            num[sl] = fmaf(v0, cc0, fmaf(v1, cc1, num[sl]));
                            sq[sl]  = fmaf(v0, v0, fmaf(v1, v1, sq[sl]));
                        }
                    }
                }
        }
        __syncthreads();
    }

    // ================= per-row cosine, block partial =======================
#pragma unroll
    for (int sl = 0; sl < 4; sl++)
#pragma unroll
        for (int o = 1; o < 4; o <<= 1) {
            num[sl] += __shfl_xor_sync(0xffffffffu, num[sl], o);
            sq[sl]  += __shfl_xor_sync(0xffffffffu, sq[sl], o);
        }
    if (q4 == 0) {
#pragma unroll
        for (int sl = 0; sl < 4; sl++) {
            int r = m0 + (sl >> 1) * 16 + (sl & 1) * 8 + g;
            red[wc * 128 + r] = num[sl];
            red[256 + wc * 128 + r] = sq[sl];
        }
    }
    __syncthreads();
    float rd = 0.f;
    if (wc == 0 && q4 == 0) {
        float cn = g_cnorm[t];
#pragma unroll
        for (int sl = 0; sl < 4; sl++) {
            int r = m0 + (sl >> 1) * 16 + (sl & 1) * 8 + g;
            float nu = red[r] + red[128 + r];
            float sv = red[256 + r] + red[384 + r];
            float vn = fmaxf(sqrtf(sv), 1e-8f);
            rd += 1.f - nu / (vn * cn);
        }
    }
#pragma unroll
    for (int o = 16; o > 0; o >>= 1) rd += __shfl_xor_sync(0xffffffffu, rd, o);
    if (wc == 0 && l == 0) red[512 + wr] = rd;
    __syncthreads();
    if (tid == 0)
        g_partial[t * NBLK + blockIdx.x] = red[512] + red[513] + red[514] + red[515];
}

__global__ void finalize_kernel(float* __restrict__ out, int out_size) {
    __shared__ float dist[T_TASKS];
    int t = threadIdx.x;
    if (t < T_TASKS) {
        float s = 0.f;
#pragma unroll
        for (int b = 0; b < NBLK; b++) s += g_partial[t * NBLK + b];
        float d = s * (1.0f / (float)B_ROWS);
        dist[t] = d;
        if (out_size >= T_TASKS) out[t] = d;
    }
    __syncthreads();
    if (t == 0) {
        int best = 0; float bv = dist[0];
        for (int i = 1; i < T_TASKS; i++)
            if (dist[i] < bv) { bv = dist[i]; best = i; }
        if (out_size >= T_TASKS + 1)      out[T_TASKS] = (float)best;
        else if (out_size >= 1 && out_size < T_TASKS) out[0] = (float)best;
    }
}

extern "C" void kernel_launch(void* const* d_in, const int* in_sizes, int n_in,
                              void* d_out, int out_size) {
    const float* t_feat = (const float*)d_in[0];
    const float* W1     = (const float*)d_in[1];
    const float* b1     = (const float*)d_in[2];
    const float* gamma  = (const float*)d_in[3];
    const float* beta   = (const float*)d_in[4];
    const float* W2     = (const float*)d_in[5];
    const float* b2     = (const float*)d_in[6];
    const float* cent   = (const float*)d_in[7];

    cudaFuncSetAttribute(router_mma, cudaFuncAttributeMaxDynamicSharedMemorySize, SMEM_BYTES);

    int cvt_blocks = (int)((CVT_TOTAL + 255) / 256);
    convert_kernel<<<cvt_blocks, 256>>>(t_feat, W1, W2);
    init_cnorm_kernel<<<T_TASKS, 128>>>(cent);
    dim3 grid(NBLK, T_TASKS);
    router_mma<<<grid, 256, SMEM_BYTES>>>(b1, gamma, beta, b2, cent);
    finalize_kernel<<<1, 64>>>((float*)d_out, out_size);
}